// round 1
// baseline (speedup 1.0000x reference)
#include <cuda_runtime.h>
#include <math.h>

#define B_      2
#define F_      16
#define H_      32
#define W_      32
#define HW      1024
#define NFRM    32            // B_*F_
#define C_      320
#define CEXP    512
#define D_INNER 1024
#define NHEADS  16
#define HEADDIM 64
#define D_STATE 128
#define D_CONV  4
#define CONV_DIM 1280         // D_INNER + 2*D_STATE
#define D_IN_PROJ 2320        // 2*D_INNER + 2*D_STATE + NHEADS
#define GROUPS  32
#define NSEQ    2048          // B_*H_*W_
#define L_      16
#define NTOK    32768         // NSEQ*L_ == NFRM*HW

// ---------------- scratch (device globals; no allocations allowed) --------
__device__ float g_t1[(long)NFRM*C_*HW];       // 10.5M  (also reused as t5)
__device__ float g_t2[(long)NFRM*C_*HW];       // 10.5M  (also reused as t6)
__device__ float g_t3[(long)NFRM*CEXP*HW];     // 16.8M  (also reused as t4)
__device__ float g_u [(long)NTOK*CEXP];        // 16.8M  (also reused as yout)
__device__ float g_zx[(long)NTOK*D_IN_PROJ];   // 76.0M
__device__ float g_xbc[(long)NTOK*CONV_DIM];   // 41.9M
__device__ float g_dt[(long)NSEQ*L_*NHEADS];
__device__ float g_y [(long)NTOK*D_INNER];     // 33.5M

// ---------------- GroupNorm -----------------------------------------------
__global__ void groupnorm_kernel(const float* __restrict__ x, const float* __restrict__ w,
                                 const float* __restrict__ b, float* __restrict__ out) {
    int n = blockIdx.x / GROUPS, g = blockIdx.x % GROUPS;
    const int CPG = C_ / GROUPS;               // 10
    const float* base = x + ((long)n*C_ + g*CPG)*HW;
    float s = 0.f, ss = 0.f;
    for (int i = threadIdx.x; i < CPG*HW; i += 256) { float v = base[i]; s += v; ss += v*v; }
    __shared__ float rs[256], rq[256];
    rs[threadIdx.x] = s; rq[threadIdx.x] = ss; __syncthreads();
    for (int o = 128; o > 0; o >>= 1) {
        if (threadIdx.x < o) { rs[threadIdx.x] += rs[threadIdx.x+o]; rq[threadIdx.x] += rq[threadIdx.x+o]; }
        __syncthreads();
    }
    float mean = rs[0] / (CPG*HW);
    float var  = rq[0] / (CPG*HW) - mean*mean;
    float inv  = rsqrtf(var + 1e-5f);
    float* ob = out + ((long)n*C_ + g*CPG)*HW;
    for (int i = threadIdx.x; i < CPG*HW; i += 256) {
        int c = g*CPG + i/HW;
        ob[i] = (base[i]-mean)*inv*w[c] + b[c];
    }
}

// ---------------- Generic tiled SGEMM --------------------------------------
// C[m][n] = sum_k A[m][k] * (BT ? B[n][k] : B[k][n])  (+ bias[m] if bias)
// 64x64 tile, BK=16, 256 threads, 4x4 per-thread. K must be multiple of 16,
// N multiple of 4 (all shapes here satisfy this). M, N bound-checked.
template<bool BT>
__global__ void gemm_kernel(const float* __restrict__ A, const float* __restrict__ B,
                            const float* __restrict__ bias, float* __restrict__ C,
                            int M, int N, int K, long sB, long sC)
{
    const float* Bb = B + (long)blockIdx.z * sB;
    float*       Cb = C + (long)blockIdx.z * sC;
    __shared__ float As[16][68];
    __shared__ float Bs[16][68];
    int tid = threadIdx.x;
    int tx = tid & 15, ty = tid >> 4;
    int m0 = blockIdx.y * 64, n0 = blockIdx.x * 64;
    int la_m = tid >> 2, la_k4 = (tid & 3) * 4;
    int lb_k = tid >> 4, lb_n4 = (tid & 15) * 4;
    float acc[4][4] = {};

    for (int k0 = 0; k0 < K; k0 += 16) {
        float4 av = make_float4(0,0,0,0);
        int am = m0 + la_m;
        if (am < M) av = *(const float4*)(A + (long)am*K + k0 + la_k4);
        As[la_k4+0][la_m] = av.x; As[la_k4+1][la_m] = av.y;
        As[la_k4+2][la_m] = av.z; As[la_k4+3][la_m] = av.w;

        if (BT) {
            float4 bv = make_float4(0,0,0,0);
            int bn = n0 + la_m;
            if (bn < N) bv = *(const float4*)(Bb + (long)bn*K + k0 + la_k4);
            Bs[la_k4+0][la_m] = bv.x; Bs[la_k4+1][la_m] = bv.y;
            Bs[la_k4+2][la_m] = bv.z; Bs[la_k4+3][la_m] = bv.w;
        } else {
            float4 bv = make_float4(0,0,0,0);
            int bn = n0 + lb_n4;
            if (bn < N) bv = *(const float4*)(Bb + (long)(k0+lb_k)*N + bn);
            *(float4*)&Bs[lb_k][lb_n4] = bv;
        }
        __syncthreads();
        #pragma unroll
        for (int k = 0; k < 16; ++k) {
            float4 a = *(const float4*)&As[k][ty*4];
            float4 bq = *(const float4*)&Bs[k][tx*4];
            float aa[4] = {a.x,a.y,a.z,a.w}, bb[4] = {bq.x,bq.y,bq.z,bq.w};
            #pragma unroll
            for (int i = 0; i < 4; ++i)
                #pragma unroll
                for (int j = 0; j < 4; ++j)
                    acc[i][j] += aa[i]*bb[j];
        }
        __syncthreads();
    }
    #pragma unroll
    for (int i = 0; i < 4; ++i) {
        int row = m0 + ty*4 + i;
        if (row >= M) continue;
        float bval = bias ? bias[row] : 0.f;
        #pragma unroll
        for (int j = 0; j < 4; ++j) {
            int col = n0 + tx*4 + j;
            if (col < N) Cb[(long)row*N + col] = acc[i][j] + bval;
        }
    }
}

// ---------------- permutes -------------------------------------------------
__global__ void perm_fwd_kernel(const float* __restrict__ t3, float* __restrict__ u) {
    long idx = (long)blockIdx.x*256 + threadIdx.x;
    if (idx >= (long)NTOK*CEXP) return;
    int e   = (int)(idx & 511);
    long t  = idx >> 9;
    int f   = (int)(t & 15);
    long bhw = t >> 4;
    int hw  = (int)(bhw & 1023);
    int b   = (int)(bhw >> 10);
    u[idx] = t3[ ((long)(b*F_+f)*CEXP + e)*HW + hw ];
}
__global__ void perm_bwd_kernel(const float* __restrict__ yo, float* __restrict__ t4) {
    long idx = (long)blockIdx.x*256 + threadIdx.x;
    if (idx >= (long)NFRM*CEXP*HW) return;
    int hw  = (int)(idx & 1023);
    long r  = idx >> 10;
    int e   = (int)(r & 511);
    long nf = r >> 9;
    int f   = (int)(nf & 15);
    int b   = (int)(nf >> 4);
    t4[idx] = yo[ (((long)(b*HW+hw)*L_ + f)*CEXP) + e ];
}

// ---------------- dt (softplus) --------------------------------------------
__global__ void dt_kernel(const float* __restrict__ zx, const float* __restrict__ dt_bias,
                          float* __restrict__ dt) {
    int idx = blockIdx.x*256 + threadIdx.x;
    if (idx >= NTOK*NHEADS) return;
    int h = idx & 15; long tok = idx >> 4;
    float v = zx[tok*D_IN_PROJ + (D_INNER+CONV_DIM) + h] + dt_bias[h];
    dt[idx] = (v > 20.f) ? v : log1pf(expf(v));
}

// ---------------- causal depthwise conv1d (k=4) + SiLU ----------------------
__global__ void conv_kernel(const float* __restrict__ zx, const float* __restrict__ cw,
                            const float* __restrict__ cb, float* __restrict__ xbc) {
    int s = blockIdx.x;
    for (int c = threadIdx.x; c < CONV_DIM; c += 256) {
        float w0 = cw[c*4+0], w1 = cw[c*4+1], w2 = cw[c*4+2], w3 = cw[c*4+3];
        float bb = cb[c];
        float v0 = 0.f, v1 = 0.f, v2 = 0.f;
        const float* base = zx + (long)s*L_*D_IN_PROJ + D_INNER + c;
        float* ob = xbc + (long)s*L_*CONV_DIM + c;
        #pragma unroll
        for (int l = 0; l < L_; ++l) {
            float v3 = base[(long)l*D_IN_PROJ];
            float o = v0*w0 + v1*w1 + v2*w2 + v3*w3 + bb;
            o = o / (1.f + expf(-o));
            ob[(long)l*CONV_DIM] = o;
            v0 = v1; v1 = v2; v2 = v3;
        }
    }
}

// ---------------- Mamba2 SSM core (per-sequence, L=16) ----------------------
__global__ void mamba_kernel(const float* __restrict__ xbc, const float* __restrict__ dtg,
                             const float* __restrict__ zx, const float* __restrict__ A_log,
                             const float* __restrict__ Dv, float* __restrict__ y)
{
    __shared__ float sB[L_][D_STATE], sC[L_][D_STATE];
    __shared__ float sScore[L_][L_];
    __shared__ float sDt[L_][NHEADS], sCum[L_][NHEADS];
    __shared__ float sW[NHEADS][L_][L_];
    int s = blockIdx.x;
    int tid = threadIdx.x;                        // 512 threads
    const float* xb = xbc + (long)s*L_*CONV_DIM;

    for (int i = tid; i < L_*D_STATE; i += 512) {
        int l = i >> 7, n = i & 127;
        sB[l][n] = xb[(long)l*CONV_DIM + D_INNER + n];
        sC[l][n] = xb[(long)l*CONV_DIM + D_INNER + D_STATE + n];
    }
    if (tid < 256) {
        int l = tid >> 4, h = tid & 15;
        sDt[l][h] = dtg[(long)s*256 + l*16 + h];
    }
    __syncthreads();
    if (tid < 256) {
        int l = tid >> 4, sp = tid & 15;
        float acc = 0.f;
        #pragma unroll 8
        for (int n = 0; n < D_STATE; ++n) acc += sC[l][n]*sB[sp][n];
        sScore[l][sp] = acc;
    } else if (tid < 272) {
        int h = tid - 256;
        float a = -expf(A_log[h]);
        float run = 0.f;
        #pragma unroll
        for (int l = 0; l < L_; ++l) { run += sDt[l][h]*a; sCum[l][h] = run; }
    }
    __syncthreads();
    for (int i = tid; i < NHEADS*L_*L_; i += 512) {
        int h = i >> 8, l = (i >> 4) & 15, sp = i & 15;
        float w;
        if (sp < l)       w = sScore[l][sp]*expf(sCum[l][h]-sCum[sp][h])*sDt[sp][h];
        else if (sp == l) w = sScore[l][l]*sDt[l][h] + Dv[h];
        else              w = 0.f;
        sW[h][l][sp] = w;
    }
    __syncthreads();

    int h = tid >> 5, lane = tid & 31;
    float x0[L_], x1[L_];
    #pragma unroll
    for (int sp = 0; sp < L_; ++sp) {
        const float* xr = xb + (long)sp*CONV_DIM + h*HEADDIM;
        x0[sp] = xr[lane];
        x1[sp] = xr[lane+32];
    }
    const float* zb = zx + (long)s*L_*D_IN_PROJ;
    float* yb = y + (long)s*L_*D_INNER;
    #pragma unroll
    for (int l = 0; l < L_; ++l) {
        float a0 = 0.f, a1 = 0.f;
        for (int sp = 0; sp <= l; ++sp) {
            float w = sW[h][l][sp];
            a0 += w*x0[sp]; a1 += w*x1[sp];
        }
        float z0 = zb[(long)l*D_IN_PROJ + h*HEADDIM + lane];
        float z1 = zb[(long)l*D_IN_PROJ + h*HEADDIM + lane + 32];
        a0 *= z0 / (1.f + expf(-z0));
        a1 *= z1 / (1.f + expf(-z1));
        yb[(long)l*D_INNER + h*HEADDIM + lane]      = a0;
        yb[(long)l*D_INNER + h*HEADDIM + lane + 32] = a1;
    }
}

// ---------------- RMSNorm ----------------------------------------------------
__global__ void rms_kernel(float* __restrict__ y, const float* __restrict__ w) {
    long row = blockIdx.x;
    float* r = y + row*D_INNER;
    float ss = 0.f;
    for (int i = threadIdx.x; i < D_INNER; i += 256) { float v = r[i]; ss += v*v; }
    __shared__ float red[256];
    red[threadIdx.x] = ss; __syncthreads();
    for (int o = 128; o > 0; o >>= 1) {
        if (threadIdx.x < o) red[threadIdx.x] += red[threadIdx.x+o];
        __syncthreads();
    }
    float scale = rsqrtf(red[0]/D_INNER + 1e-5f);
    for (int i = threadIdx.x; i < D_INNER; i += 256) r[i] = r[i]*scale*w[i];
}

// ---------------- residual add ----------------------------------------------
__global__ void final_kernel(const float* __restrict__ x, const float* __restrict__ t6,
                             const float* __restrict__ gamma, float* __restrict__ out) {
    long idx = (long)blockIdx.x*256 + threadIdx.x;
    if (idx >= (long)NFRM*C_*HW) return;
    out[idx] = x[idx] + gamma[0]*t6[idx];
}

// ---------------- launch -----------------------------------------------------
extern "C" void kernel_launch(void* const* d_in, const int* in_sizes, int n_in,
                              void* d_out, int out_size) {
    const float* x          = (const float*)d_in[0];
    const float* norm_w     = (const float*)d_in[1];
    const float* norm_b     = (const float*)d_in[2];
    const float* proj_in_w  = (const float*)d_in[3];
    const float* proj_in_b  = (const float*)d_in[4];
    const float* expand_w   = (const float*)d_in[5];
    const float* expand_b   = (const float*)d_in[6];
    const float* in_proj_w  = (const float*)d_in[7];
    const float* conv_w     = (const float*)d_in[8];
    const float* conv_b     = (const float*)d_in[9];
    const float* dt_bias    = (const float*)d_in[10];
    const float* A_log      = (const float*)d_in[11];
    const float* Dv         = (const float*)d_in[12];
    const float* rms_w      = (const float*)d_in[13];
    const float* out_proj_w = (const float*)d_in[14];
    const float* collapse_w = (const float*)d_in[15];
    const float* collapse_b = (const float*)d_in[16];
    const float* proj_out_w = (const float*)d_in[17];
    const float* proj_out_b = (const float*)d_in[18];
    const float* gamma      = (const float*)d_in[19];

    float *t1, *t2, *t3, *u, *zx, *xbc, *dt, *y;
    cudaGetSymbolAddress((void**)&t1,  g_t1);
    cudaGetSymbolAddress((void**)&t2,  g_t2);
    cudaGetSymbolAddress((void**)&t3,  g_t3);
    cudaGetSymbolAddress((void**)&u,   g_u);
    cudaGetSymbolAddress((void**)&zx,  g_zx);
    cudaGetSymbolAddress((void**)&xbc, g_xbc);
    cudaGetSymbolAddress((void**)&dt,  g_dt);
    cudaGetSymbolAddress((void**)&y,   g_y);

    // 1. GroupNorm
    groupnorm_kernel<<<NFRM*GROUPS, 256>>>(x, norm_w, norm_b, t1);

    // 2. proj_in (320 -> 320), batched NN GEMM per frame
    {
        dim3 g(HW/64, (C_+63)/64, NFRM);
        gemm_kernel<false><<<g, 256>>>(proj_in_w, t1, proj_in_b, t2,
                                       C_, HW, C_, (long)C_*HW, (long)C_*HW);
    }
    // 3. expand (320 -> 512)
    {
        dim3 g(HW/64, (CEXP+63)/64, NFRM);
        gemm_kernel<false><<<g, 256>>>(expand_w, t2, expand_b, t3,
                                       CEXP, HW, C_, (long)C_*HW, (long)CEXP*HW);
    }
    // 4. permute (n, e, hw) -> (token, e)
    perm_fwd_kernel<<<(int)(((long)NTOK*CEXP + 255)/256), 256>>>(t3, u);

    // 5. in_proj: (32768 x 2320 x 512) NT GEMM
    {
        dim3 g((D_IN_PROJ+63)/64, NTOK/64, 1);
        gemm_kernel<true><<<g, 256>>>(u, in_proj_w, nullptr, zx,
                                      NTOK, D_IN_PROJ, CEXP, 0, 0);
    }
    // 6. dt softplus + depthwise conv + SiLU
    dt_kernel<<<(NTOK*NHEADS + 255)/256, 256>>>(zx, dt_bias, dt);
    conv_kernel<<<NSEQ, 256>>>(zx, conv_w, conv_b, xbc);

    // 7. SSM core + gating
    mamba_kernel<<<NSEQ, 512>>>(xbc, dt, zx, A_log, Dv, y);

    // 8. RMSNorm
    rms_kernel<<<NTOK, 256>>>(y, rms_w);

    // 9. out_proj: (32768 x 512 x 1024) NT GEMM  (reuse u as output)
    {
        dim3 g(CEXP/64, NTOK/64, 1);
        gemm_kernel<true><<<g, 256>>>(y, out_proj_w, nullptr, u,
                                      NTOK, CEXP, D_INNER, 0, 0);
    }
    // 10. permute back (token, e) -> (n, e, hw)  (reuse t3 as t4)
    perm_bwd_kernel<<<(int)(((long)NFRM*CEXP*HW + 255)/256), 256>>>(u, t3);

    // 11. collapse (512 -> 320)
    {
        dim3 g(HW/64, (C_+63)/64, NFRM);
        gemm_kernel<false><<<g, 256>>>(collapse_w, t3, collapse_b, t1,
                                       C_, HW, CEXP, (long)CEXP*HW, (long)C_*HW);
    }
    // 12. proj_out (320 -> 320)
    {
        dim3 g(HW/64, (C_+63)/64, NFRM);
        gemm_kernel<false><<<g, 256>>>(proj_out_w, t1, proj_out_b, t2,
                                       C_, HW, C_, (long)C_*HW, (long)C_*HW);
    }
    // 13. residual
    final_kernel<<<(int)(((long)NFRM*C_*HW + 255)/256), 256>>>(x, t2, gamma, (float*)d_out);
}

// round 3
// speedup vs baseline: 3.2719x; 3.2719x over previous
#include <cuda_runtime.h>
#include <cuda_bf16.h>
#include <math.h>
#include <cstdint>

#define B_      2
#define F_      16
#define H_      32
#define W_      32
#define HW      1024
#define NFRM    32
#define C_      320
#define CEXP    512
#define D_INNER 1024
#define NHEADS  16
#define HEADDIM 64
#define D_STATE 128
#define D_CONV  4
#define CONV_DIM 1280
#define D_IN_PROJ 2320
#define GROUPS  32
#define NSEQ    2048
#define L_      16
#define NTOK    32768

// padded N (out-channel) sizes for 128-wide tiles
#define NP320   384
#define NP512   512
#define NP2320  2432

// ---------------- scratch ---------------------------------------------------
__device__ __nv_bfloat16 g_a0[(size_t)NTOK*C_];
__device__ __nv_bfloat16 g_a1[(size_t)NTOK*C_];
__device__ __nv_bfloat16 g_a2[(size_t)NTOK*CEXP];
__device__ __nv_bfloat16 g_ub[(size_t)NTOK*CEXP];
__device__ float         g_zx[(size_t)NTOK*D_IN_PROJ];
__device__ float         g_xbc[(size_t)NTOK*CONV_DIM];
__device__ float         g_dt[(size_t)NTOK*NHEADS];
__device__ float         g_y [(size_t)NTOK*D_INNER];
__device__ __nv_bfloat16 g_yb[(size_t)NTOK*D_INNER];
__device__ __nv_bfloat16 g_o1[(size_t)NTOK*CEXP];
__device__ __nv_bfloat16 g_o2[(size_t)NTOK*CEXP];
__device__ __nv_bfloat16 g_c1[(size_t)NTOK*C_];
__device__ float         g_c2[(size_t)NTOK*C_];
__device__ __nv_bfloat16 g_w1[NP320*C_];
__device__ __nv_bfloat16 g_w2[NP512*C_];
__device__ __nv_bfloat16 g_wi[(size_t)NP2320*CEXP];
__device__ __nv_bfloat16 g_wo[NP512*D_INNER];
__device__ __nv_bfloat16 g_wc[NP320*CEXP];
__device__ __nv_bfloat16 g_wp[NP320*C_];

// ---------------- PTX helpers ----------------------------------------------
__device__ __forceinline__ uint32_t smem_u32(const void* p) {
    uint32_t a;
    asm("{ .reg .u64 t; cvta.to.shared.u64 t, %1; cvt.u32.u64 %0, t; }" : "=r"(a) : "l"(p));
    return a;
}
__device__ __forceinline__ void cp16(uint32_t dst, const void* src) {
    asm volatile("cp.async.cg.shared.global [%0], [%1], 16;" :: "r"(dst), "l"(src) : "memory");
}
__device__ __forceinline__ void ldmx4(uint32_t addr, uint32_t& r0, uint32_t& r1,
                                      uint32_t& r2, uint32_t& r3) {
    asm volatile("ldmatrix.sync.aligned.m8n8.x4.shared.b16 {%0,%1,%2,%3}, [%4];"
                 : "=r"(r0), "=r"(r1), "=r"(r2), "=r"(r3) : "r"(addr));
}
__device__ __forceinline__ void mma16816(float* c, const uint32_t* a, const uint32_t* b) {
    asm volatile("mma.sync.aligned.m16n8k16.row.col.f32.bf16.bf16.f32 "
                 "{%0,%1,%2,%3}, {%4,%5,%6,%7}, {%8,%9}, {%0,%1,%2,%3};"
                 : "+f"(c[0]), "+f"(c[1]), "+f"(c[2]), "+f"(c[3])
                 : "r"(a[0]), "r"(a[1]), "r"(a[2]), "r"(a[3]), "r"(b[0]), "r"(b[1]));
}
__device__ __forceinline__ void storev(float* p, float v)         { *p = v; }
__device__ __forceinline__ void storev(__nv_bfloat16* p, float v) { *p = __float2bfloat16(v); }

// ---------------- HMMA GEMM: C[M,N] = A[M,K] @ B[N,K]^T (+bias[n]) ----------
// A, B bf16 K-major. B padded to gridDim.x*128 rows. M%128==0, K%32==0, N even.
// 128x128x32 block tile, 8 warps (4x2), warp tile 32x64, double-buffered cp.async.
// SMEM rows use 80-byte stride: bank(row) = row*20 mod 32 -> 8 consecutive rows
// cover all 32 banks; ldmatrix conflict-free.
#define GEMM_SMEM (4*128*80)
template<typename OutT>
__global__ void __launch_bounds__(256)
tc_gemm(const __nv_bfloat16* __restrict__ A, const __nv_bfloat16* __restrict__ B,
        const float* __restrict__ bias, OutT* __restrict__ C, int M, int N, int K)
{
    extern __shared__ char smraw[];
    const uint32_t sbase = smem_u32(smraw);
    const uint32_t sA[2]  = { sbase,         sbase + 10240 };
    const uint32_t sBt[2] = { sbase + 20480, sbase + 30720 };
    const int tid = threadIdx.x;
    const int lane = tid & 31, warp = tid >> 5;
    const int wm = (warp & 3) * 32, wn = (warp >> 2) * 64;
    const int m0 = blockIdx.y * 128, n0 = blockIdx.x * 128;

    float acc[2][8][4];
    #pragma unroll
    for (int i = 0; i < 2; ++i)
        #pragma unroll
        for (int j = 0; j < 8; ++j)
            #pragma unroll
            for (int k = 0; k < 4; ++k) acc[i][j][k] = 0.f;

    const int nc = K >> 5;
    auto load = [&](int i, int b) {
        const int k0 = i << 5;
        #pragma unroll
        for (int t = 0; t < 2; ++t) {
            int li = tid + t * 256;                 // 0..511
            int row = li >> 2, seg = li & 3;
            uint32_t off = (uint32_t)row * 80 + (uint32_t)seg * 16;
            cp16(sA[b]  + off, A + (size_t)(m0 + row) * K + k0 + seg * 8);
            cp16(sBt[b] + off, B + (size_t)(n0 + row) * K + k0 + seg * 8);
        }
        asm volatile("cp.async.commit_group;" ::: "memory");
    };

    load(0, 0);
    if (nc > 1) load(1, 1);

    for (int i = 0; i < nc; ++i) {
        const int b = i & 1;
        if (i + 1 < nc) asm volatile("cp.async.wait_group 1;" ::: "memory");
        else            asm volatile("cp.async.wait_group 0;" ::: "memory");
        __syncthreads();

        #pragma unroll
        for (int ks = 0; ks < 32; ks += 16) {
            uint32_t af[2][4];
            #pragma unroll
            for (int mt = 0; mt < 2; ++mt) {
                uint32_t addr = sA[b]
                    + (uint32_t)(wm + mt * 16 + (lane & 15)) * 80
                    + (uint32_t)(ks + ((lane >> 4) << 3)) * 2;
                ldmx4(addr, af[mt][0], af[mt][1], af[mt][2], af[mt][3]);
            }
            uint32_t bf[8][2];
            #pragma unroll
            for (int nt2 = 0; nt2 < 4; ++nt2) {
                int n  = wn + nt2 * 16 + (lane & 7) + ((lane >> 4) << 3);
                int kk = ks + (((lane >> 3) & 1) << 3);
                uint32_t addr = sBt[b] + (uint32_t)n * 80 + (uint32_t)kk * 2;
                ldmx4(addr, bf[nt2*2][0], bf[nt2*2][1], bf[nt2*2+1][0], bf[nt2*2+1][1]);
            }
            #pragma unroll
            for (int mt = 0; mt < 2; ++mt)
                #pragma unroll
                for (int nt = 0; nt < 8; ++nt)
                    mma16816(acc[mt][nt], af[mt], bf[nt]);
        }
        __syncthreads();
        if (i + 2 < nc) load(i + 2, b);
    }

    // epilogue: mma C layout -> global (+bias), bound-checked on N
    #pragma unroll
    for (int mt = 0; mt < 2; ++mt) {
        int row = m0 + wm + mt * 16 + (lane >> 2);
        #pragma unroll
        for (int nt = 0; nt < 8; ++nt) {
            int col = n0 + wn + nt * 8 + (lane & 3) * 2;
            if (col < N) {
                float b0 = bias ? bias[col]     : 0.f;
                float b1 = bias ? bias[col + 1] : 0.f;
                storev(C + (size_t)row * N + col,           acc[mt][nt][0] + b0);
                storev(C + (size_t)row * N + col + 1,       acc[mt][nt][1] + b1);
                storev(C + (size_t)(row + 8) * N + col,     acc[mt][nt][2] + b0);
                storev(C + (size_t)(row + 8) * N + col + 1, acc[mt][nt][3] + b1);
            }
        }
    }
}

// ---------------- weight convert + pad (fp32 [N,K] -> bf16 [Npad,K]) --------
__global__ void wconv_kernel(const float* __restrict__ w, __nv_bfloat16* __restrict__ o,
                             int N, int K, int Npad) {
    int idx = blockIdx.x * 256 + threadIdx.x;
    if (idx >= Npad * K) return;
    o[idx] = __float2bfloat16(idx < N * K ? w[idx] : 0.f);
}

// ---------------- GroupNorm -> bf16 token-major ------------------------------
__global__ void groupnorm_kernel(const float* __restrict__ x, const float* __restrict__ w,
                                 const float* __restrict__ b, __nv_bfloat16* __restrict__ out) {
    int n = blockIdx.x / GROUPS, g = blockIdx.x % GROUPS;
    const int CPG = C_ / GROUPS;               // 10
    const float* base = x + ((size_t)n * C_ + g * CPG) * HW;
    float s = 0.f, ss = 0.f;
    for (int i = threadIdx.x; i < CPG * HW; i += 256) { float v = base[i]; s += v; ss += v * v; }
    __shared__ float rs[256], rq[256];
    rs[threadIdx.x] = s; rq[threadIdx.x] = ss; __syncthreads();
    for (int o = 128; o > 0; o >>= 1) {
        if (threadIdx.x < o) { rs[threadIdx.x] += rs[threadIdx.x + o]; rq[threadIdx.x] += rq[threadIdx.x + o]; }
        __syncthreads();
    }
    float mean = rs[0] / (CPG * HW);
    float var  = rq[0] / (CPG * HW) - mean * mean;
    float inv  = rsqrtf(var + 1e-5f);
    for (int i = threadIdx.x; i < CPG * HW; i += 256) {
        int ch = i >> 10, hw = i & 1023;
        int c = g * CPG + ch;
        float v = (base[i] - mean) * inv * w[c] + b[c];
        out[((size_t)n * HW + hw) * C_ + c] = __float2bfloat16(v);
    }
}

// ---------------- row permutes (bf16, 512-wide rows) -------------------------
__global__ void perm_fwd_kernel(const __nv_bfloat16* __restrict__ src, __nv_bfloat16* __restrict__ dst) {
    int dr = blockIdx.x;                        // seq-order row (b,hw,f)
    int f = dr & 15; int t = dr >> 4; int hw = t & 1023; int bb = t >> 10;
    int sr = (bb * F_ + f) * HW + hw;           // frame-order row (b,f,hw)
    const uint2* s = (const uint2*)(src + (size_t)sr * CEXP);
    uint2* d = (uint2*)(dst + (size_t)dr * CEXP);
    d[threadIdx.x] = s[threadIdx.x];            // 128 threads x 8B = 1KB row
}
__global__ void perm_bwd_kernel(const __nv_bfloat16* __restrict__ src, __nv_bfloat16* __restrict__ dst) {
    int dr = blockIdx.x;                        // frame-order row (b,f,hw)
    int hw = dr & 1023; int t = dr >> 10; int f = t & 15; int bb = t >> 4;
    int sr = (bb * HW + hw) * L_ + f;           // seq-order row
    const uint2* s = (const uint2*)(src + (size_t)sr * CEXP);
    uint2* d = (uint2*)(dst + (size_t)dr * CEXP);
    d[threadIdx.x] = s[threadIdx.x];
}

// ---------------- dt (softplus) ----------------------------------------------
__global__ void dt_kernel(const float* __restrict__ zx, const float* __restrict__ dt_bias,
                          float* __restrict__ dt) {
    int idx = blockIdx.x * 256 + threadIdx.x;
    if (idx >= NTOK * NHEADS) return;
    int h = idx & 15; size_t tok = idx >> 4;
    float v = zx[tok * D_IN_PROJ + (D_INNER + CONV_DIM) + h] + dt_bias[h];
    dt[idx] = (v > 20.f) ? v : log1pf(expf(v));
}

// ---------------- causal depthwise conv1d (k=4) + SiLU ------------------------
__global__ void conv_kernel(const float* __restrict__ zx, const float* __restrict__ cw,
                            const float* __restrict__ cb, float* __restrict__ xbc) {
    int s = blockIdx.x;
    for (int c = threadIdx.x; c < CONV_DIM; c += 256) {
        float w0 = cw[c*4+0], w1 = cw[c*4+1], w2 = cw[c*4+2], w3 = cw[c*4+3];
        float bb = cb[c];
        float v0 = 0.f, v1 = 0.f, v2 = 0.f;
        const float* base = zx + (size_t)s * L_ * D_IN_PROJ + D_INNER + c;
        float* ob = xbc + (size_t)s * L_ * CONV_DIM + c;
        #pragma unroll
        for (int l = 0; l < L_; ++l) {
            float v3 = base[(size_t)l * D_IN_PROJ];
            float o = v0*w0 + v1*w1 + v2*w2 + v3*w3 + bb;
            o = o / (1.f + expf(-o));
            ob[(size_t)l * CONV_DIM] = o;
            v0 = v1; v1 = v2; v2 = v3;
        }
    }
}

// ---------------- Mamba2 SSM core ---------------------------------------------
__global__ void mamba_kernel(const float* __restrict__ xbc, const float* __restrict__ dtg,
                             const float* __restrict__ zx, const float* __restrict__ A_log,
                             const float* __restrict__ Dv, float* __restrict__ y)
{
    __shared__ float sB[L_][D_STATE], sC[L_][D_STATE];
    __shared__ float sScore[L_][L_];
    __shared__ float sDt[L_][NHEADS], sCum[L_][NHEADS];
    __shared__ float sW[NHEADS][L_][L_];
    int s = blockIdx.x;
    int tid = threadIdx.x;
    const float* xb = xbc + (size_t)s * L_ * CONV_DIM;

    for (int i = tid; i < L_ * D_STATE; i += 512) {
        int l = i >> 7, n = i & 127;
        sB[l][n] = xb[(size_t)l * CONV_DIM + D_INNER + n];
        sC[l][n] = xb[(size_t)l * CONV_DIM + D_INNER + D_STATE + n];
    }
    if (tid < 256) {
        int l = tid >> 4, h = tid & 15;
        sDt[l][h] = dtg[(size_t)s * 256 + l * 16 + h];
    }
    __syncthreads();
    if (tid < 256) {
        int l = tid >> 4, sp = tid & 15;
        float acc = 0.f;
        #pragma unroll 8
        for (int n = 0; n < D_STATE; ++n) acc += sC[l][n] * sB[sp][n];
        sScore[l][sp] = acc;
    } else if (tid < 272) {
        int h = tid - 256;
        float a = -expf(A_log[h]);
        float run = 0.f;
        #pragma unroll
        for (int l = 0; l < L_; ++l) { run += sDt[l][h] * a; sCum[l][h] = run; }
    }
    __syncthreads();
    for (int i = tid; i < NHEADS * L_ * L_; i += 512) {
        int h = i >> 8, l = (i >> 4) & 15, sp = i & 15;
        float w;
        if (sp < l)       w = sScore[l][sp] * expf(sCum[l][h] - sCum[sp][h]) * sDt[sp][h];
        else if (sp == l) w = sScore[l][l] * sDt[l][h] + Dv[h];
        else              w = 0.f;
        sW[h][l][sp] = w;
    }
    __syncthreads();

    int h = tid >> 5, lane = tid & 31;
    float x0[L_], x1[L_];
    #pragma unroll
    for (int sp = 0; sp < L_; ++sp) {
        const float* xr = xb + (size_t)sp * CONV_DIM + h * HEADDIM;
        x0[sp] = xr[lane];
        x1[sp] = xr[lane + 32];
    }
    const float* zb = zx + (size_t)s * L_ * D_IN_PROJ;
    float* yb = y + (size_t)s * L_ * D_INNER;
    #pragma unroll
    for (int l = 0; l < L_; ++l) {
        float a0 = 0.f, a1 = 0.f;
        for (int sp = 0; sp <= l; ++sp) {
            float w = sW[h][l][sp];
            a0 += w * x0[sp]; a1 += w * x1[sp];
        }
        float z0 = zb[(size_t)l * D_IN_PROJ + h * HEADDIM + lane];
        float z1 = zb[(size_t)l * D_IN_PROJ + h * HEADDIM + lane + 32];
        a0 *= z0 / (1.f + expf(-z0));
        a1 *= z1 / (1.f + expf(-z1));
        yb[(size_t)l * D_INNER + h * HEADDIM + lane]      = a0;
        yb[(size_t)l * D_INNER + h * HEADDIM + lane + 32] = a1;
    }
}

// ---------------- RMSNorm (fp32 in -> bf16 out) -------------------------------
__global__ void rms_kernel(const float* __restrict__ y, const float* __restrict__ w,
                           __nv_bfloat16* __restrict__ out) {
    size_t row = blockIdx.x;
    const float* r = y + row * D_INNER;
    float ss = 0.f;
    for (int i = threadIdx.x; i < D_INNER; i += 256) { float v = r[i]; ss += v * v; }
    __shared__ float red[256];
    red[threadIdx.x] = ss; __syncthreads();
    for (int o = 128; o > 0; o >>= 1) {
        if (threadIdx.x < o) red[threadIdx.x] += red[threadIdx.x + o];
        __syncthreads();
    }
    float scale = rsqrtf(red[0] / D_INNER + 1e-5f);
    __nv_bfloat16* ob = out + row * D_INNER;
    for (int i = threadIdx.x; i < D_INNER; i += 256)
        ob[i] = __float2bfloat16(r[i] * scale * w[i]);
}

// ---------------- residual (token-major c2 -> chw layout) ---------------------
__global__ void final_kernel(const float* __restrict__ x, const float* __restrict__ c2,
                             const float* __restrict__ gamma, float* __restrict__ out) {
    size_t idx = (size_t)blockIdx.x * 256 + threadIdx.x;
    if (idx >= (size_t)NFRM * C_ * HW) return;
    int hw = (int)(idx & 1023);
    size_t r = idx >> 10;
    int c = (int)(r % C_);
    int n = (int)(r / C_);
    out[idx] = x[idx] + gamma[0] * c2[((size_t)n * HW + hw) * C_ + c];
}

// ---------------- launch -------------------------------------------------------
extern "C" void kernel_launch(void* const* d_in, const int* in_sizes, int n_in,
                              void* d_out, int out_size) {
    const float* x          = (const float*)d_in[0];
    const float* norm_w     = (const float*)d_in[1];
    const float* norm_b     = (const float*)d_in[2];
    const float* proj_in_w  = (const float*)d_in[3];
    const float* proj_in_b  = (const float*)d_in[4];
    const float* expand_w   = (const float*)d_in[5];
    const float* expand_b   = (const float*)d_in[6];
    const float* in_proj_w  = (const float*)d_in[7];
    const float* conv_w     = (const float*)d_in[8];
    const float* conv_b     = (const float*)d_in[9];
    const float* dt_bias    = (const float*)d_in[10];
    const float* A_log      = (const float*)d_in[11];
    const float* Dv         = (const float*)d_in[12];
    const float* rms_w      = (const float*)d_in[13];
    const float* out_proj_w = (const float*)d_in[14];
    const float* collapse_w = (const float*)d_in[15];
    const float* collapse_b = (const float*)d_in[16];
    const float* proj_out_w = (const float*)d_in[17];
    const float* proj_out_b = (const float*)d_in[18];
    const float* gamma      = (const float*)d_in[19];

    __nv_bfloat16 *a0, *a1, *a2, *ub, *yb, *o1, *o2, *c1;
    __nv_bfloat16 *w1, *w2, *wi, *wo, *wc, *wp;
    float *zx, *xbc, *dt, *y, *c2;
    cudaGetSymbolAddress((void**)&a0, g_a0);  cudaGetSymbolAddress((void**)&a1, g_a1);
    cudaGetSymbolAddress((void**)&a2, g_a2);  cudaGetSymbolAddress((void**)&ub, g_ub);
    cudaGetSymbolAddress((void**)&zx, g_zx);  cudaGetSymbolAddress((void**)&xbc, g_xbc);
    cudaGetSymbolAddress((void**)&dt, g_dt);  cudaGetSymbolAddress((void**)&y,  g_y);
    cudaGetSymbolAddress((void**)&yb, g_yb);  cudaGetSymbolAddress((void**)&o1, g_o1);
    cudaGetSymbolAddress((void**)&o2, g_o2);  cudaGetSymbolAddress((void**)&c1, g_c1);
    cudaGetSymbolAddress((void**)&c2, g_c2);
    cudaGetSymbolAddress((void**)&w1, g_w1);  cudaGetSymbolAddress((void**)&w2, g_w2);
    cudaGetSymbolAddress((void**)&wi, g_wi);  cudaGetSymbolAddress((void**)&wo, g_wo);
    cudaGetSymbolAddress((void**)&wc, g_wc);  cudaGetSymbolAddress((void**)&wp, g_wp);

    // 0. weight conversion + padding (bf16)
    wconv_kernel<<<(NP320*C_ + 255)/256, 256>>>(proj_in_w,  w1, C_,        C_,      NP320);
    wconv_kernel<<<(NP512*C_ + 255)/256, 256>>>(expand_w,   w2, CEXP,      C_,      NP512);
    wconv_kernel<<<(NP2320*CEXP + 255)/256, 256>>>(in_proj_w, wi, D_IN_PROJ, CEXP,  NP2320);
    wconv_kernel<<<(NP512*D_INNER + 255)/256, 256>>>(out_proj_w, wo, CEXP,  D_INNER, NP512);
    wconv_kernel<<<(NP320*CEXP + 255)/256, 256>>>(collapse_w, wc, C_,       CEXP,    NP320);
    wconv_kernel<<<(NP320*C_ + 255)/256, 256>>>(proj_out_w, wp, C_,        C_,      NP320);

    // 1. GroupNorm -> bf16 token-major
    groupnorm_kernel<<<NFRM*GROUPS, 256>>>(x, norm_w, norm_b, a0);

    // 2. proj_in: [32768,320] = a0 @ w1^T + b
    { dim3 g(NP320/128, NTOK/128);
      tc_gemm<__nv_bfloat16><<<g, 256, GEMM_SMEM>>>(a0, w1, proj_in_b, a1, NTOK, C_, C_); }
    // 3. expand: [32768,512]
    { dim3 g(NP512/128, NTOK/128);
      tc_gemm<__nv_bfloat16><<<g, 256, GEMM_SMEM>>>(a1, w2, expand_b, a2, NTOK, CEXP, C_); }
    // 4. frame-order -> seq-order rows
    perm_fwd_kernel<<<NTOK, 128>>>(a2, ub);
    // 5. in_proj: [32768,2320] fp32
    { dim3 g(NP2320/128, NTOK/128);
      tc_gemm<float><<<g, 256, GEMM_SMEM>>>(ub, wi, nullptr, zx, NTOK, D_IN_PROJ, CEXP); }
    // 6. dt + conv + SiLU
    dt_kernel<<<(NTOK*NHEADS + 255)/256, 256>>>(zx, dt_bias, dt);
    conv_kernel<<<NSEQ, 256>>>(zx, conv_w, conv_b, xbc);
    // 7. SSM core + gating
    mamba_kernel<<<NSEQ, 512>>>(xbc, dt, zx, A_log, Dv, y);
    // 8. RMSNorm -> bf16
    rms_kernel<<<NTOK, 256>>>(y, rms_w, yb);
    // 9. out_proj: [32768,512] bf16
    { dim3 g(NP512/128, NTOK/128);
      tc_gemm<__nv_bfloat16><<<g, 256, GEMM_SMEM>>>(yb, wo, nullptr, o1, NTOK, CEXP, D_INNER); }
    // 10. seq-order -> frame-order rows
    perm_bwd_kernel<<<NTOK, 128>>>(o1, o2);
    // 11. collapse: [32768,320] bf16
    { dim3 g(NP320/128, NTOK/128);
      tc_gemm<__nv_bfloat16><<<g, 256, GEMM_SMEM>>>(o2, wc, collapse_b, c1, NTOK, C_, CEXP); }
    // 12. proj_out: [32768,320] fp32
    { dim3 g(NP320/128, NTOK/128);
      tc_gemm<float><<<g, 256, GEMM_SMEM>>>(c1, wp, proj_out_b, c2, NTOK, C_, C_); }
    // 13. residual
    final_kernel<<<(int)(((size_t)NFRM*C_*HW + 255)/256), 256>>>(x, c2, gamma, (float*)d_out);
}

// round 4
// speedup vs baseline: 3.2897x; 1.0054x over previous
#include <cuda_runtime.h>
#include <cuda_bf16.h>
#include <math.h>
#include <cstdint>

#define B_      2
#define F_      16
#define H_      32
#define W_      32
#define HW      1024
#define NFRM    32
#define C_      320
#define CEXP    512
#define D_INNER 1024
#define NHEADS  16
#define HEADDIM 64
#define D_STATE 128
#define D_CONV  4
#define CONV_DIM 1280
#define D_IN_PROJ 2320
#define GROUPS  32
#define NSEQ    2048
#define L_      16
#define NTOK    32768

#define NP320   384
#define NP512   512
#define NP2320  2432

// ---------------- scratch ---------------------------------------------------
__device__ __nv_bfloat16 g_a0[(size_t)NTOK*C_];
__device__ __nv_bfloat16 g_a1[(size_t)NTOK*C_];
__device__ __nv_bfloat16 g_a2[(size_t)NTOK*CEXP];
__device__ __nv_bfloat16 g_ub[(size_t)NTOK*CEXP];
__device__ __nv_bfloat16 g_zxb[(size_t)NTOK*D_IN_PROJ];
__device__ __nv_bfloat16 g_yb[(size_t)NTOK*D_INNER];
__device__ __nv_bfloat16 g_o1[(size_t)NTOK*CEXP];
__device__ __nv_bfloat16 g_o2[(size_t)NTOK*CEXP];
__device__ __nv_bfloat16 g_c1[(size_t)NTOK*C_];
__device__ float         g_c2[(size_t)NTOK*C_];
__device__ float         g_gst[NFRM*GROUPS*2];
__device__ __nv_bfloat16 g_w1[NP320*C_];
__device__ __nv_bfloat16 g_w2[NP512*C_];
__device__ __nv_bfloat16 g_wi[(size_t)NP2320*CEXP];
__device__ __nv_bfloat16 g_wo[NP512*D_INNER];
__device__ __nv_bfloat16 g_wc[NP320*CEXP];
__device__ __nv_bfloat16 g_wp[NP320*C_];

// ---------------- PTX helpers ----------------------------------------------
__device__ __forceinline__ uint32_t smem_u32(const void* p) {
    uint32_t a;
    asm("{ .reg .u64 t; cvta.to.shared.u64 t, %1; cvt.u32.u64 %0, t; }" : "=r"(a) : "l"(p));
    return a;
}
__device__ __forceinline__ void cp16(uint32_t dst, const void* src) {
    asm volatile("cp.async.cg.shared.global [%0], [%1], 16;" :: "r"(dst), "l"(src) : "memory");
}
__device__ __forceinline__ void ldmx4(uint32_t addr, uint32_t& r0, uint32_t& r1,
                                      uint32_t& r2, uint32_t& r3) {
    asm volatile("ldmatrix.sync.aligned.m8n8.x4.shared.b16 {%0,%1,%2,%3}, [%4];"
                 : "=r"(r0), "=r"(r1), "=r"(r2), "=r"(r3) : "r"(addr));
}
__device__ __forceinline__ void mma16816(float* c, const uint32_t* a, const uint32_t* b) {
    asm volatile("mma.sync.aligned.m16n8k16.row.col.f32.bf16.bf16.f32 "
                 "{%0,%1,%2,%3}, {%4,%5,%6,%7}, {%8,%9}, {%0,%1,%2,%3};"
                 : "+f"(c[0]), "+f"(c[1]), "+f"(c[2]), "+f"(c[3])
                 : "r"(a[0]), "r"(a[1]), "r"(a[2]), "r"(a[3]), "r"(b[0]), "r"(b[1]));
}
__device__ __forceinline__ void storev(float* p, float v)         { *p = v; }
__device__ __forceinline__ void storev(__nv_bfloat16* p, float v) { *p = __float2bfloat16(v); }

// ---------------- HMMA GEMM: C[M,N] = A[M,K] @ B[N,K]^T (+bias[n]) ----------
// 128x128x32 block tile, 8 warps (4x2), warp tile 32x64.
// 3-stage cp.async ring, ONE __syncthreads per k-iteration.
// 80-byte SMEM row stride -> ldmatrix conflict-free.
#define GEMM_SMEM (3*2*10240)   // 61440
template<typename OutT>
__global__ void __launch_bounds__(256)
tc_gemm(const __nv_bfloat16* __restrict__ A, const __nv_bfloat16* __restrict__ B,
        const float* __restrict__ bias, OutT* __restrict__ C, int M, int N, int K)
{
    extern __shared__ char smraw[];
    const uint32_t sbase = smem_u32(smraw);
    const int tid = threadIdx.x;
    const int lane = tid & 31, warp = tid >> 5;
    const int wm = (warp & 3) * 32, wn = (warp >> 2) * 64;
    const int m0 = blockIdx.y * 128, n0 = blockIdx.x * 128;

    float acc[2][8][4];
    #pragma unroll
    for (int i = 0; i < 2; ++i)
        #pragma unroll
        for (int j = 0; j < 8; ++j)
            #pragma unroll
            for (int k = 0; k < 4; ++k) acc[i][j][k] = 0.f;

    const int nc = K >> 5;
    auto load = [&](int i) {
        const int sl = i % 3;
        const uint32_t da = sbase + (uint32_t)sl * 20480;
        const uint32_t db = da + 10240;
        const int k0 = i << 5;
        #pragma unroll
        for (int t = 0; t < 2; ++t) {
            int li = tid + t * 256;
            int row = li >> 2, seg = li & 3;
            uint32_t off = (uint32_t)row * 80 + (uint32_t)seg * 16;
            cp16(da + off, A + (size_t)(m0 + row) * K + k0 + seg * 8);
            cp16(db + off, B + (size_t)(n0 + row) * K + k0 + seg * 8);
        }
        asm volatile("cp.async.commit_group;" ::: "memory");
    };

    load(0);
    if (nc > 1) load(1);

    for (int i = 0; i < nc; ++i) {
        if (i + 1 < nc) asm volatile("cp.async.wait_group 1;" ::: "memory");
        else            asm volatile("cp.async.wait_group 0;" ::: "memory");
        __syncthreads();
        if (i + 2 < nc) load(i + 2);   // writes slot (i+2)%3; readers done at iter i-1

        const uint32_t sA  = sbase + (uint32_t)(i % 3) * 20480;
        const uint32_t sBt = sA + 10240;
        #pragma unroll
        for (int ks = 0; ks < 32; ks += 16) {
            uint32_t af[2][4];
            #pragma unroll
            for (int mt = 0; mt < 2; ++mt) {
                uint32_t addr = sA
                    + (uint32_t)(wm + mt * 16 + (lane & 15)) * 80
                    + (uint32_t)(ks + ((lane >> 4) << 3)) * 2;
                ldmx4(addr, af[mt][0], af[mt][1], af[mt][2], af[mt][3]);
            }
            uint32_t bf[8][2];
            #pragma unroll
            for (int nt2 = 0; nt2 < 4; ++nt2) {
                int n  = wn + nt2 * 16 + (lane & 7) + ((lane >> 4) << 3);
                int kk = ks + (((lane >> 3) & 1) << 3);
                uint32_t addr = sBt + (uint32_t)n * 80 + (uint32_t)kk * 2;
                ldmx4(addr, bf[nt2*2][0], bf[nt2*2][1], bf[nt2*2+1][0], bf[nt2*2+1][1]);
            }
            #pragma unroll
            for (int mt = 0; mt < 2; ++mt)
                #pragma unroll
                for (int nt = 0; nt < 8; ++nt)
                    mma16816(acc[mt][nt], af[mt], bf[nt]);
        }
    }

    #pragma unroll
    for (int mt = 0; mt < 2; ++mt) {
        int row = m0 + wm + mt * 16 + (lane >> 2);
        #pragma unroll
        for (int nt = 0; nt < 8; ++nt) {
            int col = n0 + wn + nt * 8 + (lane & 3) * 2;
            if (col < N) {
                float b0 = bias ? bias[col]     : 0.f;
                float b1 = bias ? bias[col + 1] : 0.f;
                storev(C + (size_t)row * N + col,           acc[mt][nt][0] + b0);
                storev(C + (size_t)row * N + col + 1,       acc[mt][nt][1] + b1);
                storev(C + (size_t)(row + 8) * N + col,     acc[mt][nt][2] + b0);
                storev(C + (size_t)(row + 8) * N + col + 1, acc[mt][nt][3] + b1);
            }
        }
    }
}

// ---------------- weight convert + pad --------------------------------------
__global__ void wconv_kernel(const float* __restrict__ w, __nv_bfloat16* __restrict__ o,
                             int N, int K, int Npad) {
    int idx = blockIdx.x * 256 + threadIdx.x;
    if (idx >= Npad * K) return;
    o[idx] = __float2bfloat16(idx < N * K ? w[idx] : 0.f);
}

// ---------------- GroupNorm stats -------------------------------------------
__global__ void gn_stats(const float* __restrict__ x, float* __restrict__ st) {
    int n = blockIdx.x >> 5, g = blockIdx.x & 31;
    const int CPG = C_ / GROUPS;
    const float* base = x + ((size_t)n * C_ + g * CPG) * HW;
    float s = 0.f, ss = 0.f;
    for (int i = threadIdx.x; i < CPG * HW; i += 256) { float v = base[i]; s += v; ss += v * v; }
    __shared__ float rs[256], rq[256];
    rs[threadIdx.x] = s; rq[threadIdx.x] = ss; __syncthreads();
    for (int o = 128; o > 0; o >>= 1) {
        if (threadIdx.x < o) { rs[threadIdx.x] += rs[threadIdx.x + o]; rq[threadIdx.x] += rq[threadIdx.x + o]; }
        __syncthreads();
    }
    if (threadIdx.x == 0) {
        float mean = rs[0] / (CPG * HW);
        float var  = rq[0] / (CPG * HW) - mean * mean;
        st[blockIdx.x * 2]     = mean;
        st[blockIdx.x * 2 + 1] = rsqrtf(var + 1e-5f);
    }
}

// ---------------- GroupNorm apply + transpose -> bf16 token-major ------------
__global__ void gn_apply(const float* __restrict__ x, const float* __restrict__ st,
                         const float* __restrict__ w, const float* __restrict__ b,
                         __nv_bfloat16* __restrict__ out) {
    __shared__ float tile[32][33];
    int c0 = blockIdx.x * 32, hw0 = blockIdx.y * 32, n = blockIdx.z;
    int tx = threadIdx.x & 31, ty = threadIdx.x >> 5;   // 32x8
    #pragma unroll
    for (int r = 0; r < 4; ++r) {
        int c = c0 + ty + r * 8;
        int g = c / 10;
        float mean = st[(n * 32 + g) * 2], inv = st[(n * 32 + g) * 2 + 1];
        float v = x[((size_t)n * C_ + c) * HW + hw0 + tx];
        tile[ty + r * 8][tx] = (v - mean) * inv * w[c] + b[c];
    }
    __syncthreads();
    #pragma unroll
    for (int r = 0; r < 4; ++r) {
        int hw = hw0 + ty + r * 8;
        out[((size_t)n * HW + hw) * C_ + c0 + tx] = __float2bfloat16(tile[tx][ty + r * 8]);
    }
}

// ---------------- row permutes (bf16, 512-wide rows) -------------------------
__global__ void perm_fwd_kernel(const __nv_bfloat16* __restrict__ src, __nv_bfloat16* __restrict__ dst) {
    int dr = blockIdx.x;
    int f = dr & 15; int t = dr >> 4; int hw = t & 1023; int bb = t >> 10;
    int sr = (bb * F_ + f) * HW + hw;
    const uint2* s = (const uint2*)(src + (size_t)sr * CEXP);
    uint2* d = (uint2*)(dst + (size_t)dr * CEXP);
    d[threadIdx.x] = s[threadIdx.x];
}
__global__ void perm_bwd_kernel(const __nv_bfloat16* __restrict__ src, __nv_bfloat16* __restrict__ dst) {
    int dr = blockIdx.x;
    int hw = dr & 1023; int t = dr >> 10; int f = t & 15; int bb = t >> 4;
    int sr = (bb * HW + hw) * L_ + f;
    const uint2* s = (const uint2*)(src + (size_t)sr * CEXP);
    uint2* d = (uint2*)(dst + (size_t)dr * CEXP);
    d[threadIdx.x] = s[threadIdx.x];
}

// ---------------- fused dt + conv + SSM + gate + RMSNorm ---------------------
// one block per sequence (512 threads); zx rows are bf16.
#define CDP 1282
#define MAMBA_SMEM 167104
__global__ void __launch_bounds__(512)
mamba_fused(const __nv_bfloat16* __restrict__ zx, const float* __restrict__ cw,
            const float* __restrict__ cb, const float* __restrict__ dt_bias,
            const float* __restrict__ A_log, const float* __restrict__ Dv,
            const float* __restrict__ rms_w, __nv_bfloat16* __restrict__ yb)
{
    extern __shared__ char sm[];
    float* sx     = (float*)sm;                 // [L][CDP]   conv output (xBC)
    float* sy     = (float*)(sm + 82048);       // [L][1024]  gated y
    float* sW     = (float*)(sm + 147584);      // [16][16][16]
    float* sScore = (float*)(sm + 163968);      // [16][16]
    float* sDt    = (float*)(sm + 164992);      // [16][16]
    float* sCum   = (float*)(sm + 166016);      // [16][16]
    float* sSq    = (float*)(sm + 167040);      // [16]
    const int s = blockIdx.x, tid = threadIdx.x;
    const __nv_bfloat16* zb = zx + (size_t)s * L_ * D_IN_PROJ;

    if (tid < 256) {
        int l = tid >> 4, h = tid & 15;
        float v = __bfloat162float(zb[(size_t)l * D_IN_PROJ + D_INNER + CONV_DIM + h]) + dt_bias[h];
        sDt[l * 16 + h] = (v > 20.f) ? v : log1pf(expf(v));
    }
    if (tid < 16) sSq[tid] = 0.f;

    // depthwise conv (k=4) + SiLU into smem
    for (int c = tid; c < CONV_DIM; c += 512) {
        float w0 = cw[c*4], w1 = cw[c*4+1], w2 = cw[c*4+2], w3 = cw[c*4+3];
        float bb = cb[c];
        float v0 = 0.f, v1 = 0.f, v2 = 0.f;
        const __nv_bfloat16* base = zb + D_INNER + c;
        #pragma unroll
        for (int l = 0; l < L_; ++l) {
            float v3 = __bfloat162float(base[(size_t)l * D_IN_PROJ]);
            float o = v0*w0 + v1*w1 + v2*w2 + v3*w3 + bb;
            o = o / (1.f + expf(-o));
            sx[l * CDP + c] = o;
            v0 = v1; v1 = v2; v2 = v3;
        }
    }
    __syncthreads();

    if (tid < 256) {
        int l = tid >> 4, sp = tid & 15;
        float acc = 0.f;
        #pragma unroll 8
        for (int n = 0; n < D_STATE; ++n)
            acc += sx[l * CDP + D_INNER + D_STATE + n] * sx[sp * CDP + D_INNER + n];
        sScore[l * 16 + sp] = acc;
    } else if (tid < 272) {
        int h = tid - 256;
        float a = -expf(A_log[h]);
        float run = 0.f;
        #pragma unroll
        for (int l = 0; l < L_; ++l) { run += sDt[l * 16 + h] * a; sCum[l * 16 + h] = run; }
    }
    __syncthreads();

    for (int i = tid; i < NHEADS * 256; i += 512) {
        int h = i >> 8, l = (i >> 4) & 15, sp = i & 15;
        float w;
        if (sp < l)       w = sScore[l*16+sp] * expf(sCum[l*16+h] - sCum[sp*16+h]) * sDt[sp*16+h];
        else if (sp == l) w = sScore[l*16+l] * sDt[l*16+h] + Dv[h];
        else              w = 0.f;
        sW[(h * 16 + l) * 16 + sp] = w;
    }
    __syncthreads();

    const int h = tid >> 5, lane = tid & 31;
    float x0[L_], x1[L_];
    #pragma unroll
    for (int sp = 0; sp < L_; ++sp) {
        x0[sp] = sx[sp * CDP + h * HEADDIM + lane];
        x1[sp] = sx[sp * CDP + h * HEADDIM + lane + 32];
    }
    #pragma unroll
    for (int l = 0; l < L_; ++l) {
        float a0 = 0.f, a1 = 0.f;
        for (int sp = 0; sp <= l; ++sp) {
            float w = sW[(h * 16 + l) * 16 + sp];
            a0 += w * x0[sp]; a1 += w * x1[sp];
        }
        float z0 = __bfloat162float(zb[(size_t)l * D_IN_PROJ + h * HEADDIM + lane]);
        float z1 = __bfloat162float(zb[(size_t)l * D_IN_PROJ + h * HEADDIM + lane + 32]);
        a0 *= z0 / (1.f + expf(-z0));
        a1 *= z1 / (1.f + expf(-z1));
        sy[l * 1024 + h * HEADDIM + lane]      = a0;
        sy[l * 1024 + h * HEADDIM + lane + 32] = a1;
        float q = a0 * a0 + a1 * a1;
        #pragma unroll
        for (int off = 16; off > 0; off >>= 1) q += __shfl_xor_sync(0xffffffffu, q, off);
        if (lane == 0) atomicAdd(&sSq[l], q);
    }
    __syncthreads();
    if (tid < 16) sSq[tid] = rsqrtf(sSq[tid] / (float)D_INNER + 1e-5f);
    __syncthreads();

    __nv_bfloat16* ob = yb + (size_t)s * L_ * D_INNER;
    for (int i = tid; i < L_ * D_INNER; i += 512) {
        int l = i >> 10, d = i & 1023;
        ob[i] = __float2bfloat16(sy[l * 1024 + d] * sSq[l] * rms_w[d]);
    }
}

// ---------------- final: residual + transpose --------------------------------
__global__ void final_t(const float* __restrict__ x, const float* __restrict__ c2,
                        const float* __restrict__ gamma, float* __restrict__ out) {
    __shared__ float tile[32][33];
    int c0 = blockIdx.x * 32, hw0 = blockIdx.y * 32, n = blockIdx.z;
    int tx = threadIdx.x & 31, ty = threadIdx.x >> 5;
    #pragma unroll
    for (int r = 0; r < 4; ++r) {
        int hw = hw0 + ty + r * 8;
        tile[ty + r * 8][tx] = c2[((size_t)n * HW + hw) * C_ + c0 + tx];
    }
    __syncthreads();
    float gm = gamma[0];
    #pragma unroll
    for (int r = 0; r < 4; ++r) {
        int c = c0 + ty + r * 8;
        size_t idx = ((size_t)n * C_ + c) * HW + hw0 + tx;
        out[idx] = x[idx] + gm * tile[tx][ty + r * 8];
    }
}

// ---------------- launch -------------------------------------------------------
extern "C" void kernel_launch(void* const* d_in, const int* in_sizes, int n_in,
                              void* d_out, int out_size) {
    const float* x          = (const float*)d_in[0];
    const float* norm_w     = (const float*)d_in[1];
    const float* norm_b     = (const float*)d_in[2];
    const float* proj_in_w  = (const float*)d_in[3];
    const float* proj_in_b  = (const float*)d_in[4];
    const float* expand_w   = (const float*)d_in[5];
    const float* expand_b   = (const float*)d_in[6];
    const float* in_proj_w  = (const float*)d_in[7];
    const float* conv_w     = (const float*)d_in[8];
    const float* conv_b     = (const float*)d_in[9];
    const float* dt_bias    = (const float*)d_in[10];
    const float* A_log      = (const float*)d_in[11];
    const float* Dv         = (const float*)d_in[12];
    const float* rms_w      = (const float*)d_in[13];
    const float* out_proj_w = (const float*)d_in[14];
    const float* collapse_w = (const float*)d_in[15];
    const float* collapse_b = (const float*)d_in[16];
    const float* proj_out_w = (const float*)d_in[17];
    const float* proj_out_b = (const float*)d_in[18];
    const float* gamma      = (const float*)d_in[19];

    __nv_bfloat16 *a0, *a1, *a2, *ub, *zxb, *yb, *o1, *o2, *c1;
    __nv_bfloat16 *w1, *w2, *wi, *wo, *wc, *wp;
    float *c2, *gst;
    cudaGetSymbolAddress((void**)&a0,  g_a0);  cudaGetSymbolAddress((void**)&a1,  g_a1);
    cudaGetSymbolAddress((void**)&a2,  g_a2);  cudaGetSymbolAddress((void**)&ub,  g_ub);
    cudaGetSymbolAddress((void**)&zxb, g_zxb); cudaGetSymbolAddress((void**)&yb,  g_yb);
    cudaGetSymbolAddress((void**)&o1,  g_o1);  cudaGetSymbolAddress((void**)&o2,  g_o2);
    cudaGetSymbolAddress((void**)&c1,  g_c1);  cudaGetSymbolAddress((void**)&c2,  g_c2);
    cudaGetSymbolAddress((void**)&gst, g_gst);
    cudaGetSymbolAddress((void**)&w1, g_w1);   cudaGetSymbolAddress((void**)&w2, g_w2);
    cudaGetSymbolAddress((void**)&wi, g_wi);   cudaGetSymbolAddress((void**)&wo, g_wo);
    cudaGetSymbolAddress((void**)&wc, g_wc);   cudaGetSymbolAddress((void**)&wp, g_wp);

    cudaFuncSetAttribute(tc_gemm<float>,         cudaFuncAttributeMaxDynamicSharedMemorySize, GEMM_SMEM);
    cudaFuncSetAttribute(tc_gemm<__nv_bfloat16>, cudaFuncAttributeMaxDynamicSharedMemorySize, GEMM_SMEM);
    cudaFuncSetAttribute(mamba_fused,            cudaFuncAttributeMaxDynamicSharedMemorySize, MAMBA_SMEM);

    // 0. weight conversion + padding
    wconv_kernel<<<(NP320*C_ + 255)/256, 256>>>(proj_in_w,  w1, C_,        C_,      NP320);
    wconv_kernel<<<(NP512*C_ + 255)/256, 256>>>(expand_w,   w2, CEXP,      C_,      NP512);
    wconv_kernel<<<(NP2320*CEXP + 255)/256, 256>>>(in_proj_w, wi, D_IN_PROJ, CEXP,  NP2320);
    wconv_kernel<<<(NP512*D_INNER + 255)/256, 256>>>(out_proj_w, wo, CEXP,  D_INNER, NP512);
    wconv_kernel<<<(NP320*CEXP + 255)/256, 256>>>(collapse_w, wc, C_,       CEXP,    NP320);
    wconv_kernel<<<(NP320*C_ + 255)/256, 256>>>(proj_out_w, wp, C_,        C_,      NP320);

    // 1. GroupNorm (stats + apply/transpose)
    gn_stats<<<NFRM*GROUPS, 256>>>(x, gst);
    { dim3 g(C_/32, HW/32, NFRM); gn_apply<<<g, 256>>>(x, gst, norm_w, norm_b, a0); }

    // 2. proj_in
    { dim3 g(NP320/128, NTOK/128);
      tc_gemm<__nv_bfloat16><<<g, 256, GEMM_SMEM>>>(a0, w1, proj_in_b, a1, NTOK, C_, C_); }
    // 3. expand
    { dim3 g(NP512/128, NTOK/128);
      tc_gemm<__nv_bfloat16><<<g, 256, GEMM_SMEM>>>(a1, w2, expand_b, a2, NTOK, CEXP, C_); }
    // 4. frame-order -> seq-order
    perm_fwd_kernel<<<NTOK, 128>>>(a2, ub);
    // 5. in_proj -> bf16 zx
    { dim3 g(NP2320/128, NTOK/128);
      tc_gemm<__nv_bfloat16><<<g, 256, GEMM_SMEM>>>(ub, wi, nullptr, zxb, NTOK, D_IN_PROJ, CEXP); }
    // 6. fused dt+conv+SSM+gate+RMSNorm
    mamba_fused<<<NSEQ, 512, MAMBA_SMEM>>>(zxb, conv_w, conv_b, dt_bias, A_log, Dv, rms_w, yb);
    // 7. out_proj
    { dim3 g(NP512/128, NTOK/128);
      tc_gemm<__nv_bfloat16><<<g, 256, GEMM_SMEM>>>(yb, wo, nullptr, o1, NTOK, CEXP, D_INNER); }
    // 8. seq-order -> frame-order
    perm_bwd_kernel<<<NTOK, 128>>>(o1, o2);
    // 9. collapse
    { dim3 g(NP320/128, NTOK/128);
      tc_gemm<__nv_bfloat16><<<g, 256, GEMM_SMEM>>>(o2, wc, collapse_b, c1, NTOK, C_, CEXP); }
    // 10. proj_out (fp32 out)
    { dim3 g(NP320/128, NTOK/128);
      tc_gemm<float><<<g, 256, GEMM_SMEM>>>(c1, wp, proj_out_b, c2, NTOK, C_, C_); }
    // 11. residual + transpose
    { dim3 g(C_/32, HW/32, NFRM); final_t<<<g, 256>>>(x, c2, gamma, (float*)d_out); }
}

// round 5
// speedup vs baseline: 3.4043x; 1.0348x over previous
#include <cuda_runtime.h>
#include <cuda_bf16.h>
#include <math.h>
#include <cstdint>

#define B_      2
#define F_      16
#define H_      32
#define W_      32
#define HW      1024
#define NFRM    32
#define C_      320
#define CEXP    512
#define D_INNER 1024
#define NHEADS  16
#define HEADDIM 64
#define D_STATE 128
#define D_CONV  4
#define CONV_DIM 1280
#define D_IN_PROJ 2320
#define GROUPS  32
#define NSEQ    2048
#define L_      16
#define NTOK    32768

#define NP2320  2432
#define NPF     384

// ---------------- scratch ---------------------------------------------------
__device__ __nv_bfloat16 g_a0[(size_t)NTOK*C_];
__device__ __nv_bfloat16 g_a2[(size_t)NTOK*CEXP];
__device__ __nv_bfloat16 g_zxb[(size_t)NTOK*D_IN_PROJ];
__device__ __nv_bfloat16 g_yb[(size_t)NTOK*D_INNER];
__device__ __nv_bfloat16 g_o1[(size_t)NTOK*CEXP];
__device__ float         g_c2[(size_t)NTOK*C_];
__device__ float         g_gst[NFRM*GROUPS*2];
__device__ __nv_bfloat16 g_w21[CEXP*C_];           // fused expand∘proj_in  [512,320]
__device__ __nv_bfloat16 g_wf[(size_t)NPF*CEXP];   // fused proj_out∘collapse [384,512]
__device__ float         g_b21[CEXP];
__device__ float         g_bf[C_];
__device__ __nv_bfloat16 g_wi[(size_t)NP2320*CEXP];
__device__ __nv_bfloat16 g_wo[CEXP*D_INNER];

// ---------------- PTX helpers ----------------------------------------------
__device__ __forceinline__ uint32_t smem_u32(const void* p) {
    uint32_t a;
    asm("{ .reg .u64 t; cvta.to.shared.u64 t, %1; cvt.u32.u64 %0, t; }" : "=r"(a) : "l"(p));
    return a;
}
__device__ __forceinline__ void cp16(uint32_t dst, const void* src) {
    asm volatile("cp.async.cg.shared.global [%0], [%1], 16;" :: "r"(dst), "l"(src) : "memory");
}
__device__ __forceinline__ void ldmx4(uint32_t addr, uint32_t& r0, uint32_t& r1,
                                      uint32_t& r2, uint32_t& r3) {
    asm volatile("ldmatrix.sync.aligned.m8n8.x4.shared.b16 {%0,%1,%2,%3}, [%4];"
                 : "=r"(r0), "=r"(r1), "=r"(r2), "=r"(r3) : "r"(addr));
}
__device__ __forceinline__ void mma16816(float* c, const uint32_t* a, const uint32_t* b) {
    asm volatile("mma.sync.aligned.m16n8k16.row.col.f32.bf16.bf16.f32 "
                 "{%0,%1,%2,%3}, {%4,%5,%6,%7}, {%8,%9}, {%0,%1,%2,%3};"
                 : "+f"(c[0]), "+f"(c[1]), "+f"(c[2]), "+f"(c[3])
                 : "r"(a[0]), "r"(a[1]), "r"(a[2]), "r"(a[3]), "r"(b[0]), "r"(b[1]));
}
__device__ __forceinline__ void storev(float* p, float v)         { *p = v; }
__device__ __forceinline__ void storev(__nv_bfloat16* p, float v) { *p = __float2bfloat16(v); }

// row remap for fused permutes
template<int PERM> __device__ __forceinline__ int rowmap(int r) {
    if (PERM == 1) {            // dest seq-order, src frame-order
        int f = r & 15, hw = (r >> 4) & 1023, bb = r >> 14;
        return bb * 16384 + f * 1024 + hw;
    } else if (PERM == 2) {     // dest frame-order, src seq-order
        int hw = r & 1023, f = (r >> 10) & 15, bb = r >> 14;
        return bb * 16384 + hw * 16 + f;
    }
    return r;
}

// ---------------- HMMA GEMM: C[M,N] = A[perm][K] @ B[N,K]^T (+bias[n]) ------
// 128x128x32 block tile, 8 warps, warp tile 32x64. 3-stage cp.async ring.
// __launch_bounds__(256,2): cap regs at 128 -> 2 CTAs/SM (4 warps/SMSP).
#define GEMM_SMEM (3*2*10240)   // 61440
template<typename OutT, int PERM>
__global__ void __launch_bounds__(256, 2)
tc_gemm(const __nv_bfloat16* __restrict__ A, const __nv_bfloat16* __restrict__ B,
        const float* __restrict__ bias, OutT* __restrict__ C, int M, int N, int K)
{
    extern __shared__ char smraw[];
    const uint32_t sbase = smem_u32(smraw);
    const int tid = threadIdx.x;
    const int lane = tid & 31, warp = tid >> 5;
    const int wm = (warp & 3) * 32, wn = (warp >> 2) * 64;
    const int m0 = blockIdx.y * 128, n0 = blockIdx.x * 128;

    // per-thread source row pointers for the two A rows this thread loads
    const int ar0 = rowmap<PERM>(m0 + (tid >> 2));
    const int ar1 = rowmap<PERM>(m0 + 64 + (tid >> 2));

    float acc[2][8][4];
    #pragma unroll
    for (int i = 0; i < 2; ++i)
        #pragma unroll
        for (int j = 0; j < 8; ++j)
            #pragma unroll
            for (int k = 0; k < 4; ++k) acc[i][j][k] = 0.f;

    const int nc = K >> 5;
    auto load = [&](int i) {
        const int sl = i % 3;
        const uint32_t da = sbase + (uint32_t)sl * 20480;
        const uint32_t db = da + 10240;
        const int k0 = i << 5;
        const int row = tid >> 2, seg = tid & 3;
        const uint32_t off = (uint32_t)row * 80 + (uint32_t)seg * 16;
        cp16(da + off,               A + (size_t)ar0 * K + k0 + seg * 8);
        cp16(da + off + 64u * 80u,   A + (size_t)ar1 * K + k0 + seg * 8);
        cp16(db + off,               B + (size_t)(n0 + row) * K + k0 + seg * 8);
        cp16(db + off + 64u * 80u,   B + (size_t)(n0 + 64 + row) * K + k0 + seg * 8);
        asm volatile("cp.async.commit_group;" ::: "memory");
    };

    load(0);
    if (nc > 1) load(1);

    for (int i = 0; i < nc; ++i) {
        if (i + 1 < nc) asm volatile("cp.async.wait_group 1;" ::: "memory");
        else            asm volatile("cp.async.wait_group 0;" ::: "memory");
        __syncthreads();
        if (i + 2 < nc) load(i + 2);

        const uint32_t sA  = sbase + (uint32_t)(i % 3) * 20480;
        const uint32_t sBt = sA + 10240;
        #pragma unroll
        for (int ks = 0; ks < 32; ks += 16) {
            uint32_t af[2][4];
            #pragma unroll
            for (int mt = 0; mt < 2; ++mt) {
                uint32_t addr = sA
                    + (uint32_t)(wm + mt * 16 + (lane & 15)) * 80
                    + (uint32_t)(ks + ((lane >> 4) << 3)) * 2;
                ldmx4(addr, af[mt][0], af[mt][1], af[mt][2], af[mt][3]);
            }
            uint32_t bf[8][2];
            #pragma unroll
            for (int nt2 = 0; nt2 < 4; ++nt2) {
                int n  = wn + nt2 * 16 + (lane & 7) + ((lane >> 4) << 3);
                int kk = ks + (((lane >> 3) & 1) << 3);
                uint32_t addr = sBt + (uint32_t)n * 80 + (uint32_t)kk * 2;
                ldmx4(addr, bf[nt2*2][0], bf[nt2*2][1], bf[nt2*2+1][0], bf[nt2*2+1][1]);
            }
            #pragma unroll
            for (int mt = 0; mt < 2; ++mt)
                #pragma unroll
                for (int nt = 0; nt < 8; ++nt)
                    mma16816(acc[mt][nt], af[mt], bf[nt]);
        }
    }

    #pragma unroll
    for (int mt = 0; mt < 2; ++mt) {
        int row = m0 + wm + mt * 16 + (lane >> 2);
        #pragma unroll
        for (int nt = 0; nt < 8; ++nt) {
            int col = n0 + wn + nt * 8 + (lane & 3) * 2;
            if (col < N) {
                float b0 = bias ? bias[col]     : 0.f;
                float b1 = bias ? bias[col + 1] : 0.f;
                storev(C + (size_t)row * N + col,           acc[mt][nt][0] + b0);
                storev(C + (size_t)row * N + col + 1,       acc[mt][nt][1] + b1);
                storev(C + (size_t)(row + 8) * N + col,     acc[mt][nt][2] + b0);
                storev(C + (size_t)(row + 8) * N + col + 1, acc[mt][nt][3] + b1);
            }
        }
    }
}

// ---------------- small fp32 GEMM (weight-product fusion): C=A@B -> bf16 ----
// C[m][n] = sum_k A[m][k]*B[k][n]. 64x64x16 tile, 256 threads, 4x4/thread.
__global__ void wmul_kernel(const float* __restrict__ A, const float* __restrict__ B,
                            __nv_bfloat16* __restrict__ C, int M, int N, int K)
{
    __shared__ float As[16][68];
    __shared__ float Bs[16][68];
    int tid = threadIdx.x;
    int tx = tid & 15, ty = tid >> 4;
    int m0 = blockIdx.y * 64, n0 = blockIdx.x * 64;
    int la_m = tid >> 2, la_k4 = (tid & 3) * 4;
    int lb_k = tid >> 4, lb_n4 = (tid & 15) * 4;
    float acc[4][4] = {};
    for (int k0 = 0; k0 < K; k0 += 16) {
        float4 av = make_float4(0,0,0,0);
        if (m0 + la_m < M) av = *(const float4*)(A + (size_t)(m0+la_m)*K + k0 + la_k4);
        As[la_k4+0][la_m] = av.x; As[la_k4+1][la_m] = av.y;
        As[la_k4+2][la_m] = av.z; As[la_k4+3][la_m] = av.w;
        float4 bv = make_float4(0,0,0,0);
        if (n0 + lb_n4 < N) bv = *(const float4*)(B + (size_t)(k0+lb_k)*N + n0 + lb_n4);
        *(float4*)&Bs[lb_k][lb_n4] = bv;
        __syncthreads();
        #pragma unroll
        for (int k = 0; k < 16; ++k) {
            float4 a = *(const float4*)&As[k][ty*4];
            float4 bq = *(const float4*)&Bs[k][tx*4];
            float aa[4] = {a.x,a.y,a.z,a.w}, bb[4] = {bq.x,bq.y,bq.z,bq.w};
            #pragma unroll
            for (int i2 = 0; i2 < 4; ++i2)
                #pragma unroll
                for (int j = 0; j < 4; ++j) acc[i2][j] += aa[i2]*bb[j];
        }
        __syncthreads();
    }
    #pragma unroll
    for (int i2 = 0; i2 < 4; ++i2) {
        int row = m0 + ty*4 + i2;
        if (row >= M) continue;
        #pragma unroll
        for (int j = 0; j < 4; ++j) {
            int col = n0 + tx*4 + j;
            if (col < N) C[(size_t)row*N + col] = __float2bfloat16(acc[i2][j]);
        }
    }
}

// bias fold: bout[n] = dot(W[n,:], bin) + badd[n]
__global__ void bfold_kernel(const float* __restrict__ W, const float* __restrict__ bin,
                             const float* __restrict__ badd, float* __restrict__ bout,
                             int N, int K) {
    int n = blockIdx.x * 256 + threadIdx.x;
    if (n >= N) return;
    float s = 0.f;
    for (int k = 0; k < K; ++k) s += W[(size_t)n*K + k] * bin[k];
    bout[n] = s + badd[n];
}

// ---------------- weight convert + pad --------------------------------------
__global__ void wconv_kernel(const float* __restrict__ w, __nv_bfloat16* __restrict__ o,
                             int N, int K, int Npad) {
    int idx = blockIdx.x * 256 + threadIdx.x;
    if (idx >= Npad * K) return;
    o[idx] = __float2bfloat16(idx < N * K ? w[idx] : 0.f);
}

// ---------------- GroupNorm stats -------------------------------------------
__global__ void gn_stats(const float* __restrict__ x, float* __restrict__ st) {
    int n = blockIdx.x >> 5, g = blockIdx.x & 31;
    const int CPG = C_ / GROUPS;
    const float* base = x + ((size_t)n * C_ + g * CPG) * HW;
    float s = 0.f, ss = 0.f;
    for (int i = threadIdx.x; i < CPG * HW; i += 256) { float v = base[i]; s += v; ss += v * v; }
    __shared__ float rs[256], rq[256];
    rs[threadIdx.x] = s; rq[threadIdx.x] = ss; __syncthreads();
    for (int o = 128; o > 0; o >>= 1) {
        if (threadIdx.x < o) { rs[threadIdx.x] += rs[threadIdx.x + o]; rq[threadIdx.x] += rq[threadIdx.x + o]; }
        __syncthreads();
    }
    if (threadIdx.x == 0) {
        float mean = rs[0] / (CPG * HW);
        float var  = rq[0] / (CPG * HW) - mean * mean;
        st[blockIdx.x * 2]     = mean;
        st[blockIdx.x * 2 + 1] = rsqrtf(var + 1e-5f);
    }
}

// ---------------- GroupNorm apply + transpose -> bf16 token-major ------------
__global__ void gn_apply(const float* __restrict__ x, const float* __restrict__ st,
                         const float* __restrict__ w, const float* __restrict__ b,
                         __nv_bfloat16* __restrict__ out) {
    __shared__ float tile[32][33];
    int c0 = blockIdx.x * 32, hw0 = blockIdx.y * 32, n = blockIdx.z;
    int tx = threadIdx.x & 31, ty = threadIdx.x >> 5;
    #pragma unroll
    for (int r = 0; r < 4; ++r) {
        int c = c0 + ty + r * 8;
        int g = c / 10;
        float mean = st[(n * 32 + g) * 2], inv = st[(n * 32 + g) * 2 + 1];
        float v = x[((size_t)n * C_ + c) * HW + hw0 + tx];
        tile[ty + r * 8][tx] = (v - mean) * inv * w[c] + b[c];
    }
    __syncthreads();
    #pragma unroll
    for (int r = 0; r < 4; ++r) {
        int hw = hw0 + ty + r * 8;
        out[((size_t)n * HW + hw) * C_ + c0 + tx] = __float2bfloat16(tile[tx][ty + r * 8]);
    }
}

// ---------------- fused dt + conv + SSM + gate + RMSNorm ---------------------
#define CDP 1282
#define MAMBA_SMEM 167104
__global__ void __launch_bounds__(512)
mamba_fused(const __nv_bfloat16* __restrict__ zx, const float* __restrict__ cw,
            const float* __restrict__ cb, const float* __restrict__ dt_bias,
            const float* __restrict__ A_log, const float* __restrict__ Dv,
            const float* __restrict__ rms_w, __nv_bfloat16* __restrict__ yb)
{
    extern __shared__ char sm[];
    float* sx     = (float*)sm;                 // [L][CDP]
    float* sy     = (float*)(sm + 82048);       // [L][1024]
    float* sW     = (float*)(sm + 147584);      // [16][16][16]
    float* sScore = (float*)(sm + 163968);
    float* sDt    = (float*)(sm + 164992);
    float* sCum   = (float*)(sm + 166016);
    float* sSq    = (float*)(sm + 167040);
    const int s = blockIdx.x, tid = threadIdx.x;
    const __nv_bfloat16* zb = zx + (size_t)s * L_ * D_IN_PROJ;

    if (tid < 256) {
        int l = tid >> 4, h = tid & 15;
        float v = __bfloat162float(zb[(size_t)l * D_IN_PROJ + D_INNER + CONV_DIM + h]) + dt_bias[h];
        sDt[l * 16 + h] = (v > 20.f) ? v : log1pf(expf(v));
    }
    if (tid < 16) sSq[tid] = 0.f;

    for (int c = tid; c < CONV_DIM; c += 512) {
        float w0 = cw[c*4], w1 = cw[c*4+1], w2 = cw[c*4+2], w3 = cw[c*4+3];
        float bb = cb[c];
        float v0 = 0.f, v1 = 0.f, v2 = 0.f;
        const __nv_bfloat16* base = zb + D_INNER + c;
        #pragma unroll
        for (int l = 0; l < L_; ++l) {
            float v3 = __bfloat162float(base[(size_t)l * D_IN_PROJ]);
            float o = v0*w0 + v1*w1 + v2*w2 + v3*w3 + bb;
            o = o / (1.f + expf(-o));
            sx[l * CDP + c] = o;
            v0 = v1; v1 = v2; v2 = v3;
        }
    }
    __syncthreads();

    if (tid < 256) {
        int l = tid >> 4, sp = tid & 15;
        float acc = 0.f;
        #pragma unroll 8
        for (int n = 0; n < D_STATE; ++n)
            acc += sx[l * CDP + D_INNER + D_STATE + n] * sx[sp * CDP + D_INNER + n];
        sScore[l * 16 + sp] = acc;
    } else if (tid < 272) {
        int h = tid - 256;
        float a = -expf(A_log[h]);
        float run = 0.f;
        #pragma unroll
        for (int l = 0; l < L_; ++l) { run += sDt[l * 16 + h] * a; sCum[l * 16 + h] = run; }
    }
    __syncthreads();

    for (int i = tid; i < NHEADS * 256; i += 512) {
        int h = i >> 8, l = (i >> 4) & 15, sp = i & 15;
        float w;
        if (sp < l)       w = sScore[l*16+sp] * expf(sCum[l*16+h] - sCum[sp*16+h]) * sDt[sp*16+h];
        else if (sp == l) w = sScore[l*16+l] * sDt[l*16+h] + Dv[h];
        else              w = 0.f;
        sW[(h * 16 + l) * 16 + sp] = w;
    }
    __syncthreads();

    const int h = tid >> 5, lane = tid & 31;
    float x0[L_], x1[L_];
    #pragma unroll
    for (int sp = 0; sp < L_; ++sp) {
        x0[sp] = sx[sp * CDP + h * HEADDIM + lane];
        x1[sp] = sx[sp * CDP + h * HEADDIM + lane + 32];
    }
    #pragma unroll
    for (int l = 0; l < L_; ++l) {
        float a0 = 0.f, a1 = 0.f;
        for (int sp = 0; sp <= l; ++sp) {
            float w = sW[(h * 16 + l) * 16 + sp];
            a0 += w * x0[sp]; a1 += w * x1[sp];
        }
        float z0 = __bfloat162float(zb[(size_t)l * D_IN_PROJ + h * HEADDIM + lane]);
        float z1 = __bfloat162float(zb[(size_t)l * D_IN_PROJ + h * HEADDIM + lane + 32]);
        a0 *= z0 / (1.f + expf(-z0));
        a1 *= z1 / (1.f + expf(-z1));
        sy[l * 1024 + h * HEADDIM + lane]      = a0;
        sy[l * 1024 + h * HEADDIM + lane + 32] = a1;
        float q = a0 * a0 + a1 * a1;
        #pragma unroll
        for (int off = 16; off > 0; off >>= 1) q += __shfl_xor_sync(0xffffffffu, q, off);
        if (lane == 0) atomicAdd(&sSq[l], q);
    }
    __syncthreads();
    if (tid < 16) sSq[tid] = rsqrtf(sSq[tid] / (float)D_INNER + 1e-5f);
    __syncthreads();

    __nv_bfloat16* ob = yb + (size_t)s * L_ * D_INNER;
    for (int i = tid; i < L_ * D_INNER; i += 512) {
        int l = i >> 10, d = i & 1023;
        ob[i] = __float2bfloat16(sy[l * 1024 + d] * sSq[l] * rms_w[d]);
    }
}

// ---------------- final: residual + transpose --------------------------------
__global__ void final_t(const float* __restrict__ x, const float* __restrict__ c2,
                        const float* __restrict__ gamma, float* __restrict__ out) {
    __shared__ float tile[32][33];
    int c0 = blockIdx.x * 32, hw0 = blockIdx.y * 32, n = blockIdx.z;
    int tx = threadIdx.x & 31, ty = threadIdx.x >> 5;
    #pragma unroll
    for (int r = 0; r < 4; ++r) {
        int hw = hw0 + ty + r * 8;
        tile[ty + r * 8][tx] = c2[((size_t)n * HW + hw) * C_ + c0 + tx];
    }
    __syncthreads();
    float gm = gamma[0];
    #pragma unroll
    for (int r = 0; r < 4; ++r) {
        int c = c0 + ty + r * 8;
        size_t idx = ((size_t)n * C_ + c) * HW + hw0 + tx;
        out[idx] = x[idx] + gm * tile[tx][ty + r * 8];
    }
}

// ---------------- launch -------------------------------------------------------
extern "C" void kernel_launch(void* const* d_in, const int* in_sizes, int n_in,
                              void* d_out, int out_size) {
    const float* x          = (const float*)d_in[0];
    const float* norm_w     = (const float*)d_in[1];
    const float* norm_b     = (const float*)d_in[2];
    const float* proj_in_w  = (const float*)d_in[3];
    const float* proj_in_b  = (const float*)d_in[4];
    const float* expand_w   = (const float*)d_in[5];
    const float* expand_b   = (const float*)d_in[6];
    const float* in_proj_w  = (const float*)d_in[7];
    const float* conv_w     = (const float*)d_in[8];
    const float* conv_b     = (const float*)d_in[9];
    const float* dt_bias    = (const float*)d_in[10];
    const float* A_log      = (const float*)d_in[11];
    const float* Dv         = (const float*)d_in[12];
    const float* rms_w      = (const float*)d_in[13];
    const float* out_proj_w = (const float*)d_in[14];
    const float* collapse_w = (const float*)d_in[15];
    const float* collapse_b = (const float*)d_in[16];
    const float* proj_out_w = (const float*)d_in[17];
    const float* proj_out_b = (const float*)d_in[18];
    const float* gamma      = (const float*)d_in[19];

    __nv_bfloat16 *a0, *a2, *zxb, *yb, *o1, *w21, *wf, *wi, *wo;
    float *c2, *gst, *b21, *bfin;
    cudaGetSymbolAddress((void**)&a0,  g_a0);  cudaGetSymbolAddress((void**)&a2,  g_a2);
    cudaGetSymbolAddress((void**)&zxb, g_zxb); cudaGetSymbolAddress((void**)&yb,  g_yb);
    cudaGetSymbolAddress((void**)&o1,  g_o1);  cudaGetSymbolAddress((void**)&c2,  g_c2);
    cudaGetSymbolAddress((void**)&gst, g_gst);
    cudaGetSymbolAddress((void**)&w21, g_w21); cudaGetSymbolAddress((void**)&wf,  g_wf);
    cudaGetSymbolAddress((void**)&b21, g_b21); cudaGetSymbolAddress((void**)&bfin, g_bf);
    cudaGetSymbolAddress((void**)&wi,  g_wi);  cudaGetSymbolAddress((void**)&wo,  g_wo);

    cudaFuncSetAttribute((const void*)tc_gemm<__nv_bfloat16,0>, cudaFuncAttributeMaxDynamicSharedMemorySize, GEMM_SMEM);
    cudaFuncSetAttribute((const void*)tc_gemm<__nv_bfloat16,1>, cudaFuncAttributeMaxDynamicSharedMemorySize, GEMM_SMEM);
    cudaFuncSetAttribute((const void*)tc_gemm<float,2>,         cudaFuncAttributeMaxDynamicSharedMemorySize, GEMM_SMEM);
    cudaFuncSetAttribute((const void*)mamba_fused,              cudaFuncAttributeMaxDynamicSharedMemorySize, MAMBA_SMEM);

    // 0a. fused weight products (fp32 -> bf16)
    { dim3 g((C_+63)/64, (CEXP+63)/64);
      wmul_kernel<<<g, 256>>>(expand_w, proj_in_w, w21, CEXP, C_, C_); }     // [512,320]
    { dim3 g((CEXP+63)/64, (C_+63)/64);
      wmul_kernel<<<g, 256>>>(proj_out_w, collapse_w, wf, C_, CEXP, C_); }   // [320,512]
    bfold_kernel<<<2, 256>>>(expand_w,   proj_in_b,  expand_b,   b21,  CEXP, C_);
    bfold_kernel<<<2, 256>>>(proj_out_w, collapse_b, proj_out_b, bfin, C_,   C_);
    // 0b. big-weight conversion
    wconv_kernel<<<(NP2320*CEXP + 255)/256, 256>>>(in_proj_w, wi, D_IN_PROJ, CEXP, NP2320);
    wconv_kernel<<<(CEXP*D_INNER + 255)/256, 256>>>(out_proj_w, wo, CEXP, D_INNER, CEXP);

    // 1. GroupNorm
    gn_stats<<<NFRM*GROUPS, 256>>>(x, gst);
    { dim3 g(C_/32, HW/32, NFRM); gn_apply<<<g, 256>>>(x, gst, norm_w, norm_b, a0); }

    // 2. fused proj_in+expand: [NTOK,512] = a0 @ w21^T + b21
    { dim3 g(CEXP/128, NTOK/128);
      tc_gemm<__nv_bfloat16,0><<<g, 256, GEMM_SMEM>>>(a0, w21, b21, a2, NTOK, CEXP, C_); }
    // 3. in_proj with fused fwd permute on A rows
    { dim3 g(NP2320/128, NTOK/128);
      tc_gemm<__nv_bfloat16,1><<<g, 256, GEMM_SMEM>>>(a2, wi, nullptr, zxb, NTOK, D_IN_PROJ, CEXP); }
    // 4. fused dt+conv+SSM+gate+RMSNorm
    mamba_fused<<<NSEQ, 512, MAMBA_SMEM>>>(zxb, conv_w, conv_b, dt_bias, A_log, Dv, rms_w, yb);
    // 5. out_proj
    { dim3 g(CEXP/128, NTOK/128);
      tc_gemm<__nv_bfloat16,0><<<g, 256, GEMM_SMEM>>>(yb, wo, nullptr, o1, NTOK, CEXP, D_INNER); }
    // 6. fused collapse+proj_out with bwd permute on A rows (fp32 out)
    { dim3 g(NPF/128, NTOK/128);
      tc_gemm<float,2><<<g, 256, GEMM_SMEM>>>(o1, wf, bfin, c2, NTOK, C_, CEXP); }
    // 7. residual + transpose
    { dim3 g(C_/32, HW/32, NFRM); final_t<<<g, 256>>>(x, c2, gamma, (float*)d_out); }
}

// round 6
// speedup vs baseline: 3.6478x; 1.0715x over previous
#include <cuda_runtime.h>
#include <cuda_bf16.h>
#include <math.h>
#include <cstdint>

#define B_      2
#define F_      16
#define H_      32
#define W_      32
#define HW      1024
#define NFRM    32
#define C_      320
#define CEXP    512
#define D_INNER 1024
#define NHEADS  16
#define HEADDIM 64
#define D_STATE 128
#define D_CONV  4
#define CONV_DIM 1280
#define D_IN_PROJ 2320
#define GROUPS  32
#define NSEQ    2048
#define L_      16
#define NTOK    32768

#define NP2320  2432
#define NPF     384

// ---------------- scratch ---------------------------------------------------
__device__ __nv_bfloat16 g_a0[(size_t)NTOK*C_];
__device__ __nv_bfloat16 g_a2[(size_t)NTOK*CEXP];
__device__ __nv_bfloat16 g_zxb[(size_t)NTOK*D_IN_PROJ];
__device__ __nv_bfloat16 g_yb[(size_t)NTOK*D_INNER];
__device__ __nv_bfloat16 g_o1[(size_t)NTOK*CEXP];
__device__ float         g_c2[(size_t)NTOK*C_];
__device__ float         g_gst[NFRM*GROUPS*2];
__device__ __nv_bfloat16 g_w21[CEXP*C_];           // fused expand∘proj_in  [512,320]
__device__ __nv_bfloat16 g_wf[(size_t)NPF*CEXP];   // fused proj_out∘collapse [384(pad),512]
__device__ float         g_b21[CEXP];
__device__ float         g_bf[C_];
__device__ __nv_bfloat16 g_wi[(size_t)NP2320*CEXP];
__device__ __nv_bfloat16 g_wo[CEXP*D_INNER];

// ---------------- PTX helpers ----------------------------------------------
__device__ __forceinline__ uint32_t smem_u32(const void* p) {
    uint32_t a;
    asm("{ .reg .u64 t; cvta.to.shared.u64 t, %1; cvt.u32.u64 %0, t; }" : "=r"(a) : "l"(p));
    return a;
}
__device__ __forceinline__ void cp16(uint32_t dst, const void* src) {
    asm volatile("cp.async.cg.shared.global [%0], [%1], 16;" :: "r"(dst), "l"(src) : "memory");
}
__device__ __forceinline__ void ldmx4(uint32_t addr, uint32_t& r0, uint32_t& r1,
                                      uint32_t& r2, uint32_t& r3) {
    asm volatile("ldmatrix.sync.aligned.m8n8.x4.shared.b16 {%0,%1,%2,%3}, [%4];"
                 : "=r"(r0), "=r"(r1), "=r"(r2), "=r"(r3) : "r"(addr));
}
__device__ __forceinline__ void mma16816(float* c, const uint32_t* a, const uint32_t* b) {
    asm volatile("mma.sync.aligned.m16n8k16.row.col.f32.bf16.bf16.f32 "
                 "{%0,%1,%2,%3}, {%4,%5,%6,%7}, {%8,%9}, {%0,%1,%2,%3};"
                 : "+f"(c[0]), "+f"(c[1]), "+f"(c[2]), "+f"(c[3])
                 : "r"(a[0]), "r"(a[1]), "r"(a[2]), "r"(a[3]), "r"(b[0]), "r"(b[1]));
}
__device__ __forceinline__ void storev(float* p, float v)         { *p = v; }
__device__ __forceinline__ void storev(__nv_bfloat16* p, float v) { *p = __float2bfloat16(v); }

// row remap for fused permutes
template<int PERM> __device__ __forceinline__ int rowmap(int r) {
    if (PERM == 1) {            // dest seq-order, src frame-order
        int f = r & 15, hw = (r >> 4) & 1023, bb = r >> 14;
        return bb * 16384 + f * 1024 + hw;
    } else if (PERM == 2) {     // dest frame-order, src seq-order
        int hw = r & 1023, f = (r >> 10) & 15, bb = r >> 14;
        return bb * 16384 + hw * 16 + f;
    }
    return r;
}

// ---------------- HMMA GEMM: C[M,N] = A[perm][K] @ B[N,K]^T (+bias[n]) ------
// 128x128x64 block tile, 8 warps (4x2), warp tile 32x64.
// 3-stage cp.async ring (one __syncthreads per 64-K iter).
// 144-byte SMEM row stride -> ldmatrix conflict-free (16B*r mod 128 distinct).
// __launch_bounds__(256,2): 2 CTAs/SM; smem 110592*2 = 221KB/SM.
#define GEMM_SMEM (3*2*18432)   // 110592
template<typename OutT, int PERM>
__global__ void __launch_bounds__(256, 2)
tc_gemm(const __nv_bfloat16* __restrict__ A, const __nv_bfloat16* __restrict__ B,
        const float* __restrict__ bias, OutT* __restrict__ C, int M, int N, int K)
{
    extern __shared__ char smraw[];
    const uint32_t sbase = smem_u32(smraw);
    const int tid = threadIdx.x;
    const int lane = tid & 31, warp = tid >> 5;
    const int wm = (warp & 3) * 32, wn = (warp >> 2) * 64;
    const int m0 = blockIdx.y * 128, n0 = blockIdx.x * 128;

    // loader mapping: thread covers rows r0+32j (j=0..3), 16B segment seg
    const int seg = tid & 7, r0 = tid >> 3;
    int arows[4];
    #pragma unroll
    for (int j = 0; j < 4; ++j) arows[j] = rowmap<PERM>(m0 + r0 + j * 32);

    float acc[2][8][4];
    #pragma unroll
    for (int i = 0; i < 2; ++i)
        #pragma unroll
        for (int j = 0; j < 8; ++j)
            #pragma unroll
            for (int k = 0; k < 4; ++k) acc[i][j][k] = 0.f;

    const int nc = K >> 6;
    auto load = [&](int i) {
        const uint32_t da = sbase + (uint32_t)(i % 3) * 36864u;
        const uint32_t db = da + 18432u;
        const int k0 = i << 6;
        #pragma unroll
        for (int j = 0; j < 4; ++j) {
            int row = r0 + j * 32;
            uint32_t off = (uint32_t)row * 144u + (uint32_t)seg * 16u;
            cp16(da + off, A + (size_t)arows[j] * K + k0 + seg * 8);
            cp16(db + off, B + (size_t)(n0 + row) * K + k0 + seg * 8);
        }
        asm volatile("cp.async.commit_group;" ::: "memory");
    };

    load(0);
    if (nc > 1) load(1);

    for (int i = 0; i < nc; ++i) {
        if (i + 1 < nc) asm volatile("cp.async.wait_group 1;" ::: "memory");
        else            asm volatile("cp.async.wait_group 0;" ::: "memory");
        __syncthreads();
        if (i + 2 < nc) load(i + 2);    // slot (i+2)%3 was consumed at iter i-1

        const uint32_t sA  = sbase + (uint32_t)(i % 3) * 36864u;
        const uint32_t sBt = sA + 18432u;
        #pragma unroll
        for (int ks = 0; ks < 64; ks += 16) {
            uint32_t af[2][4];
            #pragma unroll
            for (int mt = 0; mt < 2; ++mt) {
                uint32_t addr = sA
                    + (uint32_t)(wm + mt * 16 + (lane & 15)) * 144u
                    + (uint32_t)(ks + ((lane >> 4) << 3)) * 2u;
                ldmx4(addr, af[mt][0], af[mt][1], af[mt][2], af[mt][3]);
            }
            uint32_t bf[8][2];
            #pragma unroll
            for (int nt2 = 0; nt2 < 4; ++nt2) {
                int n  = wn + nt2 * 16 + (lane & 7) + ((lane >> 4) << 3);
                int kk = ks + (((lane >> 3) & 1) << 3);
                uint32_t addr = sBt + (uint32_t)n * 144u + (uint32_t)kk * 2u;
                ldmx4(addr, bf[nt2*2][0], bf[nt2*2][1], bf[nt2*2+1][0], bf[nt2*2+1][1]);
            }
            #pragma unroll
            for (int mt = 0; mt < 2; ++mt)
                #pragma unroll
                for (int nt = 0; nt < 8; ++nt)
                    mma16816(acc[mt][nt], af[mt], bf[nt]);
        }
    }

    #pragma unroll
    for (int mt = 0; mt < 2; ++mt) {
        int row = m0 + wm + mt * 16 + (lane >> 2);
        #pragma unroll
        for (int nt = 0; nt < 8; ++nt) {
            int col = n0 + wn + nt * 8 + (lane & 3) * 2;
            if (col < N) {
                float b0 = bias ? bias[col]     : 0.f;
                float b1 = bias ? bias[col + 1] : 0.f;
                storev(C + (size_t)row * N + col,           acc[mt][nt][0] + b0);
                storev(C + (size_t)row * N + col + 1,       acc[mt][nt][1] + b1);
                storev(C + (size_t)(row + 8) * N + col,     acc[mt][nt][2] + b0);
                storev(C + (size_t)(row + 8) * N + col + 1, acc[mt][nt][3] + b1);
            }
        }
    }
}

// ---------------- weight product: C[m][n] = sum_k A[m][k]*B[k][n] -> bf16 ----
// warp-per-row x 32-col slabs; B loads coalesced across lanes.
__global__ void wmul_kernel(const float* __restrict__ A, const float* __restrict__ B,
                            __nv_bfloat16* __restrict__ C, int M, int N, int K)
{
    int lane = threadIdx.x & 31, w = threadIdx.x >> 5;
    int m = blockIdx.y * 8 + w;
    int n = blockIdx.x * 32 + lane;
    if (m >= M || n >= N) return;
    float s = 0.f;
    const float* ar = A + (size_t)m * K;
    const float* bc = B + n;
    for (int k = 0; k < K; ++k) s += ar[k] * bc[(size_t)k * N];
    C[(size_t)m * N + n] = __float2bfloat16(s);
}

// bias fold: bout[n] = dot(W[n,:], bin) + badd[n]  (warp per output)
__global__ void bfold_kernel(const float* __restrict__ W, const float* __restrict__ bin,
                             const float* __restrict__ badd, float* __restrict__ bout,
                             int N, int K) {
    int lane = threadIdx.x & 31, w = threadIdx.x >> 5;
    int n = blockIdx.x * 8 + w;
    if (n >= N) return;
    float s = 0.f;
    for (int k = lane; k < K; k += 32) s += W[(size_t)n * K + k] * bin[k];
    #pragma unroll
    for (int off = 16; off > 0; off >>= 1) s += __shfl_xor_sync(0xffffffffu, s, off);
    if (lane == 0) bout[n] = s + badd[n];
}

// ---------------- weight convert + pad --------------------------------------
__global__ void wconv_kernel(const float* __restrict__ w, __nv_bfloat16* __restrict__ o,
                             int N, int K, int Npad) {
    int idx = blockIdx.x * 256 + threadIdx.x;
    if (idx >= Npad * K) return;
    o[idx] = __float2bfloat16(idx < N * K ? w[idx] : 0.f);
}

// ---------------- GroupNorm stats -------------------------------------------
__global__ void gn_stats(const float* __restrict__ x, float* __restrict__ st) {
    int n = blockIdx.x >> 5, g = blockIdx.x & 31;
    const int CPG = C_ / GROUPS;
    const float* base = x + ((size_t)n * C_ + g * CPG) * HW;
    float s = 0.f, ss = 0.f;
    for (int i = threadIdx.x; i < CPG * HW; i += 256) { float v = base[i]; s += v; ss += v * v; }
    __shared__ float rs[256], rq[256];
    rs[threadIdx.x] = s; rq[threadIdx.x] = ss; __syncthreads();
    for (int o = 128; o > 0; o >>= 1) {
        if (threadIdx.x < o) { rs[threadIdx.x] += rs[threadIdx.x + o]; rq[threadIdx.x] += rq[threadIdx.x + o]; }
        __syncthreads();
    }
    if (threadIdx.x == 0) {
        float mean = rs[0] / (CPG * HW);
        float var  = rq[0] / (CPG * HW) - mean * mean;
        st[blockIdx.x * 2]     = mean;
        st[blockIdx.x * 2 + 1] = rsqrtf(var + 1e-5f);
    }
}

// ---------------- GroupNorm apply + transpose -> bf16 token-major ------------
__global__ void gn_apply(const float* __restrict__ x, const float* __restrict__ st,
                         const float* __restrict__ w, const float* __restrict__ b,
                         __nv_bfloat16* __restrict__ out) {
    __shared__ float tile[32][33];
    int c0 = blockIdx.x * 32, hw0 = blockIdx.y * 32, n = blockIdx.z;
    int tx = threadIdx.x & 31, ty = threadIdx.x >> 5;
    #pragma unroll
    for (int r = 0; r < 4; ++r) {
        int c = c0 + ty + r * 8;
        int g = c / 10;
        float mean = st[(n * 32 + g) * 2], inv = st[(n * 32 + g) * 2 + 1];
        float v = x[((size_t)n * C_ + c) * HW + hw0 + tx];
        tile[ty + r * 8][tx] = (v - mean) * inv * w[c] + b[c];
    }
    __syncthreads();
    #pragma unroll
    for (int r = 0; r < 4; ++r) {
        int hw = hw0 + ty + r * 8;
        out[((size_t)n * HW + hw) * C_ + c0 + tx] = __float2bfloat16(tile[tx][ty + r * 8]);
    }
}

// ---------------- fused dt + conv + SSM + gate + RMSNorm ---------------------
#define CDP 1282
#define MAMBA_SMEM 167104
__global__ void __launch_bounds__(512)
mamba_fused(const __nv_bfloat16* __restrict__ zx, const float* __restrict__ cw,
            const float* __restrict__ cb, const float* __restrict__ dt_bias,
            const float* __restrict__ A_log, const float* __restrict__ Dv,
            const float* __restrict__ rms_w, __nv_bfloat16* __restrict__ yb)
{
    extern __shared__ char sm[];
    float* sx     = (float*)sm;                 // [L][CDP]
    float* sy     = (float*)(sm + 82048);       // [L][1024]
    float* sW     = (float*)(sm + 147584);      // [16][16][16]
    float* sScore = (float*)(sm + 163968);
    float* sDt    = (float*)(sm + 164992);
    float* sCum   = (float*)(sm + 166016);
    float* sSq    = (float*)(sm + 167040);
    const int s = blockIdx.x, tid = threadIdx.x;
    const __nv_bfloat16* zb = zx + (size_t)s * L_ * D_IN_PROJ;

    if (tid < 256) {
        int l = tid >> 4, h = tid & 15;
        float v = __bfloat162float(zb[(size_t)l * D_IN_PROJ + D_INNER + CONV_DIM + h]) + dt_bias[h];
        sDt[l * 16 + h] = (v > 20.f) ? v : log1pf(expf(v));
    }
    if (tid < 16) sSq[tid] = 0.f;

    for (int c = tid; c < CONV_DIM; c += 512) {
        float w0 = cw[c*4], w1 = cw[c*4+1], w2 = cw[c*4+2], w3 = cw[c*4+3];
        float bb = cb[c];
        float v0 = 0.f, v1 = 0.f, v2 = 0.f;
        const __nv_bfloat16* base = zb + D_INNER + c;
        #pragma unroll
        for (int l = 0; l < L_; ++l) {
            float v3 = __bfloat162float(base[(size_t)l * D_IN_PROJ]);
            float o = v0*w0 + v1*w1 + v2*w2 + v3*w3 + bb;
            o = o / (1.f + expf(-o));
            sx[l * CDP + c] = o;
            v0 = v1; v1 = v2; v2 = v3;
        }
    }
    __syncthreads();

    if (tid < 256) {
        int l = tid >> 4, sp = tid & 15;
        float acc = 0.f;
        #pragma unroll 8
        for (int n = 0; n < D_STATE; ++n)
            acc += sx[l * CDP + D_INNER + D_STATE + n] * sx[sp * CDP + D_INNER + n];
        sScore[l * 16 + sp] = acc;
    } else if (tid < 272) {
        int h = tid - 256;
        float a = -expf(A_log[h]);
        float run = 0.f;
        #pragma unroll
        for (int l = 0; l < L_; ++l) { run += sDt[l * 16 + h] * a; sCum[l * 16 + h] = run; }
    }
    __syncthreads();

    for (int i = tid; i < NHEADS * 256; i += 512) {
        int h = i >> 8, l = (i >> 4) & 15, sp = i & 15;
        float w;
        if (sp < l)       w = sScore[l*16+sp] * expf(sCum[l*16+h] - sCum[sp*16+h]) * sDt[sp*16+h];
        else if (sp == l) w = sScore[l*16+l] * sDt[l*16+h] + Dv[h];
        else              w = 0.f;
        sW[(h * 16 + l) * 16 + sp] = w;
    }
    __syncthreads();

    const int h = tid >> 5, lane = tid & 31;
    float x0[L_], x1[L_];
    #pragma unroll
    for (int sp = 0; sp < L_; ++sp) {
        x0[sp] = sx[sp * CDP + h * HEADDIM + lane];
        x1[sp] = sx[sp * CDP + h * HEADDIM + lane + 32];
    }
    #pragma unroll
    for (int l = 0; l < L_; ++l) {
        float a0 = 0.f, a1 = 0.f;
        for (int sp = 0; sp <= l; ++sp) {
            float w = sW[(h * 16 + l) * 16 + sp];
            a0 += w * x0[sp]; a1 += w * x1[sp];
        }
        float z0 = __bfloat162float(zb[(size_t)l * D_IN_PROJ + h * HEADDIM + lane]);
        float z1 = __bfloat162float(zb[(size_t)l * D_IN_PROJ + h * HEADDIM + lane + 32]);
        a0 *= z0 / (1.f + expf(-z0));
        a1 *= z1 / (1.f + expf(-z1));
        sy[l * 1024 + h * HEADDIM + lane]      = a0;
        sy[l * 1024 + h * HEADDIM + lane + 32] = a1;
        float q = a0 * a0 + a1 * a1;
        #pragma unroll
        for (int off = 16; off > 0; off >>= 1) q += __shfl_xor_sync(0xffffffffu, q, off);
        if (lane == 0) atomicAdd(&sSq[l], q);
    }
    __syncthreads();
    if (tid < 16) sSq[tid] = rsqrtf(sSq[tid] / (float)D_INNER + 1e-5f);
    __syncthreads();

    __nv_bfloat16* ob = yb + (size_t)s * L_ * D_INNER;
    for (int i = tid; i < L_ * D_INNER; i += 512) {
        int l = i >> 10, d = i & 1023;
        ob[i] = __float2bfloat16(sy[l * 1024 + d] * sSq[l] * rms_w[d]);
    }
}

// ---------------- final: residual + transpose --------------------------------
__global__ void final_t(const float* __restrict__ x, const float* __restrict__ c2,
                        const float* __restrict__ gamma, float* __restrict__ out) {
    __shared__ float tile[32][33];
    int c0 = blockIdx.x * 32, hw0 = blockIdx.y * 32, n = blockIdx.z;
    int tx = threadIdx.x & 31, ty = threadIdx.x >> 5;
    #pragma unroll
    for (int r = 0; r < 4; ++r) {
        int hw = hw0 + ty + r * 8;
        tile[ty + r * 8][tx] = c2[((size_t)n * HW + hw) * C_ + c0 + tx];
    }
    __syncthreads();
    float gm = gamma[0];
    #pragma unroll
    for (int r = 0; r < 4; ++r) {
        int c = c0 + ty + r * 8;
        size_t idx = ((size_t)n * C_ + c) * HW + hw0 + tx;
        out[idx] = x[idx] + gm * tile[tx][ty + r * 8];
    }
}

// ---------------- launch -------------------------------------------------------
extern "C" void kernel_launch(void* const* d_in, const int* in_sizes, int n_in,
                              void* d_out, int out_size) {
    const float* x          = (const float*)d_in[0];
    const float* norm_w     = (const float*)d_in[1];
    const float* norm_b     = (const float*)d_in[2];
    const float* proj_in_w  = (const float*)d_in[3];
    const float* proj_in_b  = (const float*)d_in[4];
    const float* expand_w   = (const float*)d_in[5];
    const float* expand_b   = (const float*)d_in[6];
    const float* in_proj_w  = (const float*)d_in[7];
    const float* conv_w     = (const float*)d_in[8];
    const float* conv_b     = (const float*)d_in[9];
    const float* dt_bias    = (const float*)d_in[10];
    const float* A_log      = (const float*)d_in[11];
    const float* Dv         = (const float*)d_in[12];
    const float* rms_w      = (const float*)d_in[13];
    const float* out_proj_w = (const float*)d_in[14];
    const float* collapse_w = (const float*)d_in[15];
    const float* collapse_b = (const float*)d_in[16];
    const float* proj_out_w = (const float*)d_in[17];
    const float* proj_out_b = (const float*)d_in[18];
    const float* gamma      = (const float*)d_in[19];

    __nv_bfloat16 *a0, *a2, *zxb, *yb, *o1, *w21, *wf, *wi, *wo;
    float *c2, *gst, *b21, *bfin;
    cudaGetSymbolAddress((void**)&a0,  g_a0);  cudaGetSymbolAddress((void**)&a2,  g_a2);
    cudaGetSymbolAddress((void**)&zxb, g_zxb); cudaGetSymbolAddress((void**)&yb,  g_yb);
    cudaGetSymbolAddress((void**)&o1,  g_o1);  cudaGetSymbolAddress((void**)&c2,  g_c2);
    cudaGetSymbolAddress((void**)&gst, g_gst);
    cudaGetSymbolAddress((void**)&w21, g_w21); cudaGetSymbolAddress((void**)&wf,  g_wf);
    cudaGetSymbolAddress((void**)&b21, g_b21); cudaGetSymbolAddress((void**)&bfin, g_bf);
    cudaGetSymbolAddress((void**)&wi,  g_wi);  cudaGetSymbolAddress((void**)&wo,  g_wo);

    cudaFuncSetAttribute((const void*)tc_gemm<__nv_bfloat16,0>, cudaFuncAttributeMaxDynamicSharedMemorySize, GEMM_SMEM);
    cudaFuncSetAttribute((const void*)tc_gemm<__nv_bfloat16,1>, cudaFuncAttributeMaxDynamicSharedMemorySize, GEMM_SMEM);
    cudaFuncSetAttribute((const void*)tc_gemm<float,2>,         cudaFuncAttributeMaxDynamicSharedMemorySize, GEMM_SMEM);
    cudaFuncSetAttribute((const void*)mamba_fused,              cudaFuncAttributeMaxDynamicSharedMemorySize, MAMBA_SMEM);

    // 0a. fused weight products (fp32 -> bf16), parallel
    { dim3 g((C_+31)/32, (CEXP+7)/8);
      wmul_kernel<<<g, 256>>>(expand_w, proj_in_w, w21, CEXP, C_, C_); }     // [512,320]
    { dim3 g((CEXP+31)/32, (C_+7)/8);
      wmul_kernel<<<g, 256>>>(proj_out_w, collapse_w, wf, C_, CEXP, C_); }   // [320,512]
    bfold_kernel<<<CEXP/8, 256>>>(expand_w,   proj_in_b,  expand_b,   b21,  CEXP, C_);
    bfold_kernel<<<C_/8,   256>>>(proj_out_w, collapse_b, proj_out_b, bfin, C_,   C_);
    // 0b. big-weight conversion
    wconv_kernel<<<(NP2320*CEXP + 255)/256, 256>>>(in_proj_w, wi, D_IN_PROJ, CEXP, NP2320);
    wconv_kernel<<<(CEXP*D_INNER + 255)/256, 256>>>(out_proj_w, wo, CEXP, D_INNER, CEXP);

    // 1. GroupNorm
    gn_stats<<<NFRM*GROUPS, 256>>>(x, gst);
    { dim3 g(C_/32, HW/32, NFRM); gn_apply<<<g, 256>>>(x, gst, norm_w, norm_b, a0); }

    // 2. fused proj_in+expand: [NTOK,512] = a0 @ w21^T + b21
    { dim3 g(CEXP/128, NTOK/128);
      tc_gemm<__nv_bfloat16,0><<<g, 256, GEMM_SMEM>>>(a0, w21, b21, a2, NTOK, CEXP, C_); }
    // 3. in_proj with fused fwd permute on A rows
    { dim3 g(NP2320/128, NTOK/128);
      tc_gemm<__nv_bfloat16,1><<<g, 256, GEMM_SMEM>>>(a2, wi, nullptr, zxb, NTOK, D_IN_PROJ, CEXP); }
    // 4. fused dt+conv+SSM+gate+RMSNorm
    mamba_fused<<<NSEQ, 512, MAMBA_SMEM>>>(zxb, conv_w, conv_b, dt_bias, A_log, Dv, rms_w, yb);
    // 5. out_proj
    { dim3 g(CEXP/128, NTOK/128);
      tc_gemm<__nv_bfloat16,0><<<g, 256, GEMM_SMEM>>>(yb, wo, nullptr, o1, NTOK, CEXP, D_INNER); }
    // 6. fused collapse+proj_out with bwd permute on A rows (fp32 out)
    { dim3 g(NPF/128, NTOK/128);
      tc_gemm<float,2><<<g, 256, GEMM_SMEM>>>(o1, wf, bfin, c2, NTOK, C_, CEXP); }
    // 7. residual + transpose
    { dim3 g(C_/32, HW/32, NFRM); final_t<<<g, 256>>>(x, c2, gamma, (float*)d_out); }
}